// round 1
// baseline (speedup 1.0000x reference)
#include <cuda_runtime.h>
#include <math.h>
#include <stdint.h>

// ---------------- problem constants ----------------
#define Bz 2
#define Dz 8
#define Cz 256
#define Wz 84
#define Hz 84
#define HEADS 8
#define HD 32
#define NT 98            // tokens per window (2*7*7)
#define NW 576           // windows per batch (4*12*12)
#define BW (Bz*NW)       // 1152 window-batches
#define TOK (BW*NT)      // 112896 tokens
#define HID 1024

// ---------------- scratch (device globals; allocation-free) ----------------
__device__ float g_xp  [(size_t)TOK*Cz];   // shortcut, layout (B,D,H,W,C)
__device__ float g_xw  [(size_t)TOK*Cz];   // LN1+windowed tokens; reused for proj out
__device__ float g_qkv [(size_t)TOK*3*Cz];
__device__ float g_ao  [(size_t)TOK*Cz];   // attention output (windowed order)
__device__ float g_xres[(size_t)TOK*Cz];   // (B,D,H,W,C)
__device__ float g_ln2 [(size_t)TOK*Cz];
__device__ float g_hid [(size_t)TOK*HID];
__device__ float g_y   [(size_t)TOK*Cz];

// ---------------- 1: transpose in (B,D,C,W,H) -> (B,D,H,W,C) ----------------
__global__ void k_transpose_in(const float* __restrict__ x) {
    __shared__ float tile[32][33];
    int bz = blockIdx.z;           // bd*W + w
    int bd = bz / Wz, w = bz % Wz;
    int h0 = blockIdx.x * 32, c0 = blockIdx.y * 32;
    #pragma unroll
    for (int j = 0; j < 32; j += 8) {
        int c = c0 + threadIdx.y + j;
        int h = h0 + threadIdx.x;
        if (h < Hz)
            tile[threadIdx.y + j][threadIdx.x] =
                x[(((size_t)bd * Cz + c) * Wz + w) * Hz + h];
    }
    __syncthreads();
    #pragma unroll
    for (int j = 0; j < 32; j += 8) {
        int c = c0 + threadIdx.x;
        int h = h0 + threadIdx.y + j;
        if (h < Hz)
            g_xp[(((size_t)bd * Hz + h) * Wz + w) * Cz + c] =
                tile[threadIdx.x][threadIdx.y + j];
    }
}

// map windowed token t -> source/destination token index in (B,D,H,W) space
// (cyclic shift by +SS; same map is used for partition-source and reverse-dest)
__device__ __forceinline__ int map_token(int t) {
    int b   = t / (NW * NT);
    int rem = t % (NW * NT);
    int wi = rem / NT, n = rem % NT;
    int d2 = wi / 144, h2 = (wi / 12) % 12, w2 = wi % 12;
    int dd = n / 49, r = n % 49, hh = r / 7, ww = r % 7;
    int d = d2 * 2 + dd, h = h2 * 7 + hh, w = w2 * 7 + ww;
    int ds = (d + 1) & 7;
    int hs = h + 3; if (hs >= Hz) hs -= Hz;
    int ws = w + 3; if (ws >= Wz) ws -= Wz;
    return ((b * Dz + ds) * Hz + hs) * Wz + ws;
}

// block reduce helpers (256 threads)
__device__ __forceinline__ void blockMeanVar(float v, float& mean, float& invstd) {
    __shared__ float sbuf[16];
    float s1 = v, s2 = v * v;
    #pragma unroll
    for (int o = 16; o; o >>= 1) {
        s1 += __shfl_down_sync(0xffffffffu, s1, o);
        s2 += __shfl_down_sync(0xffffffffu, s2, o);
    }
    int wp = threadIdx.x >> 5, ln = threadIdx.x & 31;
    if (!ln) { sbuf[wp] = s1; sbuf[8 + wp] = s2; }
    __syncthreads();
    float m = 0.f, q = 0.f;
    #pragma unroll
    for (int i = 0; i < 8; i++) { m += sbuf[i]; q += sbuf[8 + i]; }
    m *= (1.f / Cz);
    q = q * (1.f / Cz) - m * m;
    mean = m;
    invstd = rsqrtf(q + 1e-5f);
}

// ---------------- 2: LN1 + shift + window partition ----------------
__global__ void k_ln_part(const float* __restrict__ g, const float* __restrict__ bta) {
    int t = blockIdx.x;
    int srct = map_token(t);
    int c = threadIdx.x;
    float v = g_xp[(size_t)srct * Cz + c];
    float m, inv;
    blockMeanVar(v, m, inv);
    g_xw[(size_t)t * Cz + c] = (v - m) * inv * g[c] + bta[c];
}

// ---------------- generic SIMT GEMM: out[M,N] = A[M,K] @ Wt[N,K]^T ----------------
// BM=BN=64, BK=32, 256 threads, 4x4 per thread. M % 64 == 0, N % 64 == 0, K % 32 == 0.
template <int ACT, bool HAS_BIAS, bool HAS_RES>
__global__ void k_gemm(const float* __restrict__ A, const float* __restrict__ Wt,
                       const float* __restrict__ bias, const float* __restrict__ res,
                       float* __restrict__ out, int M, int N, int K) {
    __shared__ float As[32][65];
    __shared__ float Bs[32][65];
    int bm = blockIdx.x * 64, bn = blockIdx.y * 64;
    int tid = threadIdx.x;
    int tx = tid & 15, ty = tid >> 4;
    float acc[4][4] = {};
    for (int k0 = 0; k0 < K; k0 += 32) {
        #pragma unroll
        for (int l = 0; l < 2; l++) {
            int i  = tid + l * 256;
            int row = i >> 3;
            int kq  = (i & 7) << 2;
            float4 a = *(const float4*)(A  + (size_t)(bm + row) * K + k0 + kq);
            As[kq + 0][row] = a.x; As[kq + 1][row] = a.y;
            As[kq + 2][row] = a.z; As[kq + 3][row] = a.w;
            float4 b = *(const float4*)(Wt + (size_t)(bn + row) * K + k0 + kq);
            Bs[kq + 0][row] = b.x; Bs[kq + 1][row] = b.y;
            Bs[kq + 2][row] = b.z; Bs[kq + 3][row] = b.w;
        }
        __syncthreads();
        #pragma unroll
        for (int kk = 0; kk < 32; kk++) {
            float av[4], bv[4];
            #pragma unroll
            for (int i = 0; i < 4; i++) av[i] = As[kk][ty * 4 + i];
            #pragma unroll
            for (int j = 0; j < 4; j++) bv[j] = Bs[kk][tx * 4 + j];
            #pragma unroll
            for (int i = 0; i < 4; i++)
                #pragma unroll
                for (int j = 0; j < 4; j++)
                    acc[i][j] = fmaf(av[i], bv[j], acc[i][j]);
        }
        __syncthreads();
    }
    #pragma unroll
    for (int i = 0; i < 4; i++) {
        int m = bm + ty * 4 + i;
        #pragma unroll
        for (int j = 0; j < 4; j++) {
            int n = bn + tx * 4 + j;
            float v = acc[i][j];
            if (HAS_BIAS) v += bias[n];
            if (ACT == 1) v = 0.5f * v * (1.f + erff(v * 0.70710678118654752f));
            if (HAS_RES)  v += res[(size_t)m * N + n];
            out[(size_t)m * N + n] = v;
        }
    }
}

// ---------------- 4: attention per (head, window) ----------------
__global__ void k_attn(const float* __restrict__ rpb) {
    extern __shared__ float sm[];
    float* qs = sm;                 // NT x 33
    float* ks = qs + NT * 33;
    float* vs = ks + NT * 33;
    float* S  = vs + NT * 33;       // NT x 99
    __shared__ int regn[NT];
    __shared__ unsigned char ddv[NT], hhv[NT], wwv[NT];

    int head = blockIdx.x, bwin = blockIdx.y;
    int tid = threadIdx.x;
    const float scale = 0.17677669529663687f;  // 32^-0.5

    size_t base = (size_t)bwin * NT * (3 * Cz) + head * HD;
    for (int i = tid; i < NT * HD; i += 256) {
        int n = i >> 5, j = i & 31;
        const float* p = g_qkv + base + (size_t)n * (3 * Cz) + j;
        qs[n * 33 + j] = p[0] * scale;
        ks[n * 33 + j] = p[Cz];
        vs[n * 33 + j] = p[2 * Cz];
    }
    if (tid < NT) {
        int wi = bwin % NW;
        int dd = tid / 49, r = tid % 49, hh = r / 7, ww = r % 7;
        ddv[tid] = (unsigned char)dd; hhv[tid] = (unsigned char)hh; wwv[tid] = (unsigned char)ww;
        int gd = (wi / 144) * 2 + dd;
        int gh = ((wi / 12) % 12) * 7 + hh;
        int gw = (wi % 12) * 7 + ww;
        int rd = gd < 6  ? 0 : (gd < 7  ? 1 : 2);
        int rh = gh < 77 ? 0 : (gh < 81 ? 1 : 2);
        int rw = gw < 77 ? 0 : (gw < 81 ? 1 : 2);
        regn[tid] = rd * 9 + rh * 3 + rw;
    }
    __syncthreads();

    int tx = tid & 15, ty = tid >> 4;
    int rn[7], cn[7];
    #pragma unroll
    for (int i = 0; i < 7; i++) {
        rn[i] = min(ty + 16 * i, NT - 1);
        cn[i] = min(tx + 16 * i, NT - 1);
    }
    float acc[7][7];
    #pragma unroll
    for (int i = 0; i < 7; i++)
        #pragma unroll
        for (int j = 0; j < 7; j++) acc[i][j] = 0.f;

    for (int k = 0; k < HD; k++) {
        float av[7], bv[7];
        #pragma unroll
        for (int i = 0; i < 7; i++) av[i] = qs[rn[i] * 33 + k];
        #pragma unroll
        for (int j = 0; j < 7; j++) bv[j] = ks[cn[j] * 33 + k];
        #pragma unroll
        for (int i = 0; i < 7; i++)
            #pragma unroll
            for (int j = 0; j < 7; j++)
                acc[i][j] = fmaf(av[i], bv[j], acc[i][j]);
    }

    // bias + mask, write S
    #pragma unroll
    for (int i = 0; i < 7; i++) {
        int n = ty + 16 * i;
        if (n < NT) {
            int dn = ddv[n], hn = hhv[n], wn = wwv[n], rg = regn[n];
            #pragma unroll
            for (int j = 0; j < 7; j++) {
                int mcol = tx + 16 * j;
                if (mcol < NT) {
                    int idx = (dn - (int)ddv[mcol] + 1) * 169
                            + (hn - (int)hhv[mcol] + 6) * 13
                            + (wn - (int)wwv[mcol] + 6);
                    float bias = rpb[idx * HEADS + head];
                    float mk = (rg != regn[mcol]) ? -100.f : 0.f;
                    S[n * 99 + mcol] = acc[i][j] + bias + mk;
                }
            }
        }
    }
    __syncthreads();

    // softmax: one warp per row
    int warp = tid >> 5, lane = tid & 31;
    for (int r = warp; r < NT; r += 8) {
        float* row = S + r * 99;
        float mx = -1e30f;
        for (int c = lane; c < NT; c += 32) mx = fmaxf(mx, row[c]);
        #pragma unroll
        for (int o = 16; o; o >>= 1) mx = fmaxf(mx, __shfl_xor_sync(0xffffffffu, mx, o));
        float sum = 0.f;
        for (int c = lane; c < NT; c += 32) { float e = __expf(row[c] - mx); row[c] = e; sum += e; }
        #pragma unroll
        for (int o = 16; o; o >>= 1) sum += __shfl_xor_sync(0xffffffffu, sum, o);
        float inv = 1.f / sum;
        for (int c = lane; c < NT; c += 32) row[c] *= inv;
    }
    __syncthreads();

    // O = P @ V : each thread rows rn[0..6], cols {tx, tx+16}
    float o0[7] = {}, o1[7] = {};
    for (int m = 0; m < NT; m++) {
        float v0 = vs[m * 33 + tx];
        float v1 = vs[m * 33 + tx + 16];
        #pragma unroll
        for (int i = 0; i < 7; i++) {
            float p = S[rn[i] * 99 + m];
            o0[i] = fmaf(p, v0, o0[i]);
            o1[i] = fmaf(p, v1, o1[i]);
        }
    }
    #pragma unroll
    for (int i = 0; i < 7; i++) {
        int n = ty + 16 * i;
        if (n < NT) {
            size_t ob = ((size_t)bwin * NT + n) * Cz + head * HD;
            g_ao[ob + tx]      = o0[i];
            g_ao[ob + tx + 16] = o1[i];
        }
    }
}

// ---------------- 6: window reverse + unshift + residual + LN2 ----------------
__global__ void k_rev_res_ln2(const float* __restrict__ g2, const float* __restrict__ b2) {
    int t = blockIdx.x;
    int ft = map_token(t);   // same map as partition source
    int c = threadIdx.x;
    float v = g_xw[(size_t)t * Cz + c] + g_xp[(size_t)ft * Cz + c];
    g_xres[(size_t)ft * Cz + c] = v;
    float m, inv;
    blockMeanVar(v, m, inv);
    g_ln2[(size_t)ft * Cz + c] = (v - m) * inv * g2[c] + b2[c];
}

// ---------------- 9: transpose out (B,D,H,W,C) -> (B,D,C,W,H) ----------------
__global__ void k_transpose_out(float* __restrict__ out) {
    __shared__ float tile[32][33];
    int bz = blockIdx.z;
    int bd = bz / Wz, w = bz % Wz;
    int h0 = blockIdx.x * 32, c0 = blockIdx.y * 32;
    #pragma unroll
    for (int j = 0; j < 32; j += 8) {
        int c = c0 + threadIdx.x;
        int h = h0 + threadIdx.y + j;
        if (h < Hz)
            tile[threadIdx.y + j][threadIdx.x] =
                g_y[(((size_t)bd * Hz + h) * Wz + w) * Cz + c];
    }
    __syncthreads();
    #pragma unroll
    for (int j = 0; j < 32; j += 8) {
        int h = h0 + threadIdx.x;
        int c = c0 + threadIdx.y + j;
        if (h < Hz)
            out[(((size_t)bd * Cz + c) * Wz + w) * Hz + h] =
                tile[threadIdx.x][threadIdx.y + j];
    }
}

// ---------------- launch ----------------
extern "C" void kernel_launch(void* const* d_in, const int* in_sizes, int n_in,
                              void* d_out, int out_size) {
    const float* x      = (const float*)d_in[0];
    const float* n1g    = (const float*)d_in[1];
    const float* n1b    = (const float*)d_in[2];
    const float* qkv_w  = (const float*)d_in[3];
    const float* rpb    = (const float*)d_in[4];
    const float* proj_w = (const float*)d_in[5];
    const float* proj_b = (const float*)d_in[6];
    const float* n2g    = (const float*)d_in[7];
    const float* n2b    = (const float*)d_in[8];
    const float* fc1_w  = (const float*)d_in[9];
    const float* fc1_b  = (const float*)d_in[10];
    const float* fc2_w  = (const float*)d_in[11];
    const float* fc2_b  = (const float*)d_in[12];
    float* out = (float*)d_out;

    void* p;
    cudaGetSymbolAddress(&p, g_xw);   float* xw   = (float*)p;
    cudaGetSymbolAddress(&p, g_qkv);  float* qkv  = (float*)p;
    cudaGetSymbolAddress(&p, g_ao);   float* ao   = (float*)p;
    cudaGetSymbolAddress(&p, g_xres); float* xres = (float*)p;
    cudaGetSymbolAddress(&p, g_ln2);  float* ln2  = (float*)p;
    cudaGetSymbolAddress(&p, g_hid);  float* hid  = (float*)p;
    cudaGetSymbolAddress(&p, g_y);    float* y    = (float*)p;

    dim3 tb(32, 8);
    dim3 tg(3, 8, Bz * Dz * Wz);

    // 1. transpose in
    k_transpose_in<<<tg, tb>>>(x);
    // 2. LN1 + shift + partition
    k_ln_part<<<TOK, 256>>>(n1g, n1b);
    // 3. qkv GEMM (no bias)
    k_gemm<0, false, false><<<dim3(TOK / 64, (3 * Cz) / 64), 256>>>(
        xw, qkv_w, nullptr, nullptr, qkv, TOK, 3 * Cz, Cz);
    // 4. attention
    const int ATTN_SMEM = (3 * NT * 33 + NT * 99) * 4;
    cudaFuncSetAttribute(k_attn, cudaFuncAttributeMaxDynamicSharedMemorySize, ATTN_SMEM);
    k_attn<<<dim3(HEADS, BW), 256, ATTN_SMEM>>>(rpb);
    // 5. proj GEMM (+bias) -> reuse g_xw
    k_gemm<0, true, false><<<dim3(TOK / 64, Cz / 64), 256>>>(
        ao, proj_w, proj_b, nullptr, xw, TOK, Cz, Cz);
    // 6. reverse + residual + LN2
    k_rev_res_ln2<<<TOK, 256>>>(n2g, n2b);
    // 7. fc1 GEMM + GELU
    k_gemm<1, true, false><<<dim3(TOK / 64, HID / 64), 256>>>(
        ln2, fc1_w, fc1_b, nullptr, hid, TOK, HID, Cz);
    // 8. fc2 GEMM + bias + residual
    k_gemm<0, true, true><<<dim3(TOK / 64, Cz / 64), 256>>>(
        hid, fc2_w, fc2_b, xres, y, TOK, Cz, HID);
    // 9. transpose out
    k_transpose_out<<<tg, tb>>>(out);
}

// round 3
// speedup vs baseline: 2.4039x; 2.4039x over previous
#include <cuda_runtime.h>
#include <cuda_bf16.h>
#include <math.h>
#include <stdint.h>

// ---------------- problem constants ----------------
#define Bz 2
#define Dz 8
#define Cz 256
#define Wz 84
#define Hz 84
#define HEADS 8
#define HD 32
#define NT 98            // tokens per window (2*7*7)
#define NW 576           // windows per batch (4*12*12)
#define BW (Bz*NW)       // 1152 window-batches
#define TOK (BW*NT)      // 112896 tokens
#define HID 1024

// ---------------- scratch (device globals; allocation-free) ----------------
__device__ float g_xp  [(size_t)TOK*Cz];   // shortcut, layout (B,D,H,W,C)
__device__ float g_xw  [(size_t)TOK*Cz];   // LN1+windowed tokens; reused for proj out
__device__ float g_qkv [(size_t)TOK*3*Cz];
__device__ float g_ao  [(size_t)TOK*Cz];   // attention output (windowed order)
__device__ float g_xres[(size_t)TOK*Cz];   // (B,D,H,W,C)
__device__ float g_ln2 [(size_t)TOK*Cz];
__device__ float g_hid [(size_t)TOK*HID];
__device__ float g_y   [(size_t)TOK*Cz];

// ---------------- helpers ----------------
__device__ __forceinline__ uint32_t smem_u32(const void* p) {
    uint32_t a;
    asm("{ .reg .u64 t; cvta.to.shared.u64 t, %1; cvt.u32.u64 %0, t; }" : "=r"(a) : "l"(p));
    return a;
}
__device__ __forceinline__ uint32_t pack2bf(float x, float y) {
    __nv_bfloat162 t = __floats2bfloat162_rn(x, y);
    return *(uint32_t*)&t;
}
__device__ __forceinline__ float bf_hi(float x) {
    return __bfloat162float(__float2bfloat16(x));
}
__device__ __forceinline__ void ldsm4(uint32_t addr, uint32_t& r0, uint32_t& r1,
                                      uint32_t& r2, uint32_t& r3) {
    asm volatile("ldmatrix.sync.aligned.m8n8.x4.shared.b16 {%0,%1,%2,%3}, [%4];"
                 : "=r"(r0), "=r"(r1), "=r"(r2), "=r"(r3) : "r"(addr));
}
__device__ __forceinline__ void mma_bf16(float* d, const uint32_t* a, const uint32_t* b) {
    asm volatile(
        "mma.sync.aligned.m16n8k16.row.col.f32.bf16.bf16.f32 "
        "{%0,%1,%2,%3}, {%4,%5,%6,%7}, {%8,%9}, {%0,%1,%2,%3};"
        : "+f"(d[0]), "+f"(d[1]), "+f"(d[2]), "+f"(d[3])
        : "r"(a[0]), "r"(a[1]), "r"(a[2]), "r"(a[3]), "r"(b[0]), "r"(b[1]));
}

// ---------------- 1: transpose in (B,D,C,W,H) -> (B,D,H,W,C) ----------------
__global__ void k_transpose_in(const float* __restrict__ x) {
    __shared__ float tile[32][33];
    int bz = blockIdx.z;
    int bd = bz / Wz, w = bz % Wz;
    int h0 = blockIdx.x * 32, c0 = blockIdx.y * 32;
    #pragma unroll
    for (int j = 0; j < 32; j += 8) {
        int c = c0 + threadIdx.y + j;
        int h = h0 + threadIdx.x;
        if (h < Hz)
            tile[threadIdx.y + j][threadIdx.x] =
                x[(((size_t)bd * Cz + c) * Wz + w) * Hz + h];
    }
    __syncthreads();
    #pragma unroll
    for (int j = 0; j < 32; j += 8) {
        int c = c0 + threadIdx.x;
        int h = h0 + threadIdx.y + j;
        if (h < Hz)
            g_xp[(((size_t)bd * Hz + h) * Wz + w) * Cz + c] =
                tile[threadIdx.x][threadIdx.y + j];
    }
}

__device__ __forceinline__ int map_token(int t) {
    int b   = t / (NW * NT);
    int rem = t % (NW * NT);
    int wi = rem / NT, n = rem % NT;
    int d2 = wi / 144, h2 = (wi / 12) % 12, w2 = wi % 12;
    int dd = n / 49, r = n % 49, hh = r / 7, ww = r % 7;
    int d = d2 * 2 + dd, h = h2 * 7 + hh, w = w2 * 7 + ww;
    int ds = (d + 1) & 7;
    int hs = h + 3; if (hs >= Hz) hs -= Hz;
    int ws = w + 3; if (ws >= Wz) ws -= Wz;
    return ((b * Dz + ds) * Hz + hs) * Wz + ws;
}

__device__ __forceinline__ void blockMeanVar(float v, float& mean, float& invstd) {
    __shared__ float sbuf[16];
    float s1 = v, s2 = v * v;
    #pragma unroll
    for (int o = 16; o; o >>= 1) {
        s1 += __shfl_down_sync(0xffffffffu, s1, o);
        s2 += __shfl_down_sync(0xffffffffu, s2, o);
    }
    int wp = threadIdx.x >> 5, ln = threadIdx.x & 31;
    if (!ln) { sbuf[wp] = s1; sbuf[8 + wp] = s2; }
    __syncthreads();
    float m = 0.f, q = 0.f;
    #pragma unroll
    for (int i = 0; i < 8; i++) { m += sbuf[i]; q += sbuf[8 + i]; }
    m *= (1.f / Cz);
    q = q * (1.f / Cz) - m * m;
    mean = m;
    invstd = rsqrtf(q + 1e-5f);
}

// ---------------- 2: LN1 + shift + window partition ----------------
__global__ void k_ln_part(const float* __restrict__ g, const float* __restrict__ bta) {
    int t = blockIdx.x;
    int srct = map_token(t);
    int c = threadIdx.x;
    float v = g_xp[(size_t)srct * Cz + c];
    float m, inv;
    blockMeanVar(v, m, inv);
    g_xw[(size_t)t * Cz + c] = (v - m) * inv * g[c] + bta[c];
}

// ---------------- mma.sync split-bf16 GEMM: out[M,N] = A[M,K] @ Wt[N,K]^T ----
// 128x128 tile, BK=32. fp32 -> (hi,lo) bf16 in smem; 3 HMMA passes: hh+lh+hl.
// smem rows padded to 40 bf16 (80 B): ldmatrix row stride = 5 mod 8 quad-banks
// -> conflict-free. B stored [N][K] so plain ldmatrix yields row.col b-frags.
#define PADK 40
template <int ACT, bool HAS_BIAS, bool HAS_RES>
__global__ __launch_bounds__(256, 2) void k_gemm_mma(
    const float* __restrict__ A, const float* __restrict__ Wt,
    const float* __restrict__ bias, const float* __restrict__ res,
    float* __restrict__ out, int M, int N, int K) {
    __shared__ __nv_bfloat16 sA[2][128 * PADK];   // [hi/lo]
    __shared__ __nv_bfloat16 sB[2][128 * PADK];
    int tid = threadIdx.x, lane = tid & 31, wid = tid >> 5;
    int bm = blockIdx.y * 128, bn = blockIdx.x * 128;
    int wm = (wid & 1) * 64, wn = (wid >> 1) * 32;

    uint32_t baseAH = smem_u32(sA[0]), baseAL = smem_u32(sA[1]);
    uint32_t baseBH = smem_u32(sB[0]), baseBL = smem_u32(sB[1]);

    // per-lane ldmatrix offsets (element units, k0 added later)
    int aRow = wm + (lane & 15);
    int aCol = (lane >> 4) * 8;
    int bRow = wn + ((lane >> 4) << 3) + (lane & 7);
    int bCol = ((lane >> 3) & 1) * 8;

    float acc[4][4][4];
    #pragma unroll
    for (int i = 0; i < 4; i++)
        #pragma unroll
        for (int j = 0; j < 4; j++)
            #pragma unroll
            for (int c = 0; c < 4; c++) acc[i][j][c] = 0.f;

    for (int k0c = 0; k0c < K; k0c += 32) {
        if (k0c) __syncthreads();
        #pragma unroll
        for (int it = 0; it < 4; it++) {
            int idx = it * 256 + tid;
            int row = idx >> 3, c4 = (idx & 7) << 2;
            float4 a = *(const float4*)(A + (size_t)(bm + row) * K + k0c + c4);
            float4 b = *(const float4*)(Wt + (size_t)(bn + row) * K + k0c + c4);
            int so = row * PADK + c4;
            float hx, hy, hz, hw;
            hx = bf_hi(a.x); hy = bf_hi(a.y); hz = bf_hi(a.z); hw = bf_hi(a.w);
            *(uint2*)&sA[0][so] = make_uint2(pack2bf(a.x, a.y), pack2bf(a.z, a.w));
            *(uint2*)&sA[1][so] = make_uint2(pack2bf(a.x - hx, a.y - hy),
                                             pack2bf(a.z - hz, a.w - hw));
            hx = bf_hi(b.x); hy = bf_hi(b.y); hz = bf_hi(b.z); hw = bf_hi(b.w);
            *(uint2*)&sB[0][so] = make_uint2(pack2bf(b.x, b.y), pack2bf(b.z, b.w));
            *(uint2*)&sB[1][so] = make_uint2(pack2bf(b.x - hx, b.y - hy),
                                             pack2bf(b.z - hz, b.w - hw));
        }
        __syncthreads();
        #pragma unroll
        for (int kk = 0; kk < 2; kk++) {
            int k0 = kk * 16;
            uint32_t aH[4][4], aL[4][4], bb[8];
            #pragma unroll
            for (int mi = 0; mi < 4; mi++) {
                uint32_t off = (uint32_t)(((aRow + mi * 16) * PADK + k0 + aCol) * 2);
                ldsm4(baseAH + off, aH[mi][0], aH[mi][1], aH[mi][2], aH[mi][3]);
                ldsm4(baseAL + off, aL[mi][0], aL[mi][1], aL[mi][2], aL[mi][3]);
            }
            #pragma unroll
            for (int p = 0; p < 2; p++) {
                uint32_t off = (uint32_t)(((bRow + p * 16) * PADK + k0 + bCol) * 2);
                ldsm4(baseBH + off, bb[p * 4 + 0], bb[p * 4 + 1], bb[p * 4 + 2], bb[p * 4 + 3]);
            }
            #pragma unroll
            for (int mi = 0; mi < 4; mi++)
                #pragma unroll
                for (int ni = 0; ni < 4; ni++)
                    mma_bf16(acc[mi][ni], aH[mi], &bb[ni * 2]);
            #pragma unroll
            for (int mi = 0; mi < 4; mi++)
                #pragma unroll
                for (int ni = 0; ni < 4; ni++)
                    mma_bf16(acc[mi][ni], aL[mi], &bb[ni * 2]);
            #pragma unroll
            for (int p = 0; p < 2; p++) {
                uint32_t off = (uint32_t)(((bRow + p * 16) * PADK + k0 + bCol) * 2);
                ldsm4(baseBL + off, bb[p * 4 + 0], bb[p * 4 + 1], bb[p * 4 + 2], bb[p * 4 + 3]);
            }
            #pragma unroll
            for (int mi = 0; mi < 4; mi++)
                #pragma unroll
                for (int ni = 0; ni < 4; ni++)
                    mma_bf16(acc[mi][ni], aH[mi], &bb[ni * 2]);
        }
    }

    // epilogue: c-frag rows lane/4, lane/4+8; cols (lane&3)*2, +1
    int orow = lane >> 2, ocol = (lane & 3) * 2;
    #pragma unroll
    for (int mi = 0; mi < 4; mi++) {
        int m0 = bm + wm + mi * 16;
        #pragma unroll
        for (int ni = 0; ni < 4; ni++) {
            int n = bn + wn + ni * 8 + ocol;
            float bi0 = 0.f, bi1 = 0.f;
            if (HAS_BIAS) { bi0 = bias[n]; bi1 = bias[n + 1]; }
            #pragma unroll
            for (int half = 0; half < 2; half++) {
                int m = m0 + orow + half * 8;
                float v0 = acc[mi][ni][half * 2 + 0] + bi0;
                float v1 = acc[mi][ni][half * 2 + 1] + bi1;
                if (ACT == 1) {
                    v0 = 0.5f * v0 * (1.f + erff(v0 * 0.70710678118654752f));
                    v1 = 0.5f * v1 * (1.f + erff(v1 * 0.70710678118654752f));
                }
                if (HAS_RES) {
                    const float2 r2 = *(const float2*)(res + (size_t)m * N + n);
                    v0 += r2.x; v1 += r2.y;
                }
                *(float2*)(out + (size_t)m * N + n) = make_float2(v0, v1);
            }
        }
    }
}

// ---------------- 4: attention per (head, window) ----------------
__global__ void k_attn(const float* __restrict__ rpb) {
    extern __shared__ float sm[];
    float* qs = sm;                 // NT x 33
    float* ks = qs + NT * 33;
    float* vs = ks + NT * 33;
    float* S  = vs + NT * 33;       // NT x 99
    __shared__ int regn[NT];
    __shared__ unsigned char ddv[NT], hhv[NT], wwv[NT];

    int head = blockIdx.x, bwin = blockIdx.y;
    int tid = threadIdx.x;
    const float scale = 0.17677669529663687f;

    size_t base = (size_t)bwin * NT * (3 * Cz) + head * HD;
    for (int i = tid; i < NT * HD; i += 256) {
        int n = i >> 5, j = i & 31;
        const float* p = g_qkv + base + (size_t)n * (3 * Cz) + j;
        qs[n * 33 + j] = p[0] * scale;
        ks[n * 33 + j] = p[Cz];
        vs[n * 33 + j] = p[2 * Cz];
    }
    if (tid < NT) {
        int wi = bwin % NW;
        int dd = tid / 49, r = tid % 49, hh = r / 7, ww = r % 7;
        ddv[tid] = (unsigned char)dd; hhv[tid] = (unsigned char)hh; wwv[tid] = (unsigned char)ww;
        int gd = (wi / 144) * 2 + dd;
        int gh = ((wi / 12) % 12) * 7 + hh;
        int gw = (wi % 12) * 7 + ww;
        int rd = gd < 6  ? 0 : (gd < 7  ? 1 : 2);
        int rh = gh < 77 ? 0 : (gh < 81 ? 1 : 2);
        int rw = gw < 77 ? 0 : (gw < 81 ? 1 : 2);
        regn[tid] = rd * 9 + rh * 3 + rw;
    }
    __syncthreads();

    int tx = tid & 15, ty = tid >> 4;
    int rn[7], cn[7];
    #pragma unroll
    for (int i = 0; i < 7; i++) {
        rn[i] = min(ty + 16 * i, NT - 1);
        cn[i] = min(tx + 16 * i, NT - 1);
    }
    float acc[7][7];
    #pragma unroll
    for (int i = 0; i < 7; i++)
        #pragma unroll
        for (int j = 0; j < 7; j++) acc[i][j] = 0.f;

    for (int k = 0; k < HD; k++) {
        float av[7], bv[7];
        #pragma unroll
        for (int i = 0; i < 7; i++) av[i] = qs[rn[i] * 33 + k];
        #pragma unroll
        for (int j = 0; j < 7; j++) bv[j] = ks[cn[j] * 33 + k];
        #pragma unroll
        for (int i = 0; i < 7; i++)
            #pragma unroll
            for (int j = 0; j < 7; j++)
                acc[i][j] = fmaf(av[i], bv[j], acc[i][j]);
    }

    #pragma unroll
    for (int i = 0; i < 7; i++) {
        int n = ty + 16 * i;
        if (n < NT) {
            int dn = ddv[n], hn = hhv[n], wn = wwv[n], rg = regn[n];
            #pragma unroll
            for (int j = 0; j < 7; j++) {
                int mcol = tx + 16 * j;
                if (mcol < NT) {
                    int idx = (dn - (int)ddv[mcol] + 1) * 169
                            + (hn - (int)hhv[mcol] + 6) * 13
                            + (wn - (int)wwv[mcol] + 6);
                    float bias = rpb[idx * HEADS + head];
                    float mk = (rg != regn[mcol]) ? -100.f : 0.f;
                    S[n * 99 + mcol] = acc[i][j] + bias + mk;
                }
            }
        }
    }
    __syncthreads();

    int warp = tid >> 5, lane = tid & 31;
    for (int r = warp; r < NT; r += 8) {
        float* row = S + r * 99;
        float mx = -1e30f;
        for (int c = lane; c < NT; c += 32) mx = fmaxf(mx, row[c]);
        #pragma unroll
        for (int o = 16; o; o >>= 1) mx = fmaxf(mx, __shfl_xor_sync(0xffffffffu, mx, o));
        float sum = 0.f;
        for (int c = lane; c < NT; c += 32) { float e = __expf(row[c] - mx); row[c] = e; sum += e; }
        #pragma unroll
        for (int o = 16; o; o >>= 1) sum += __shfl_xor_sync(0xffffffffu, sum, o);
        float inv = 1.f / sum;
        for (int c = lane; c < NT; c += 32) row[c] *= inv;
    }
    __syncthreads();

    float o0[7] = {}, o1[7] = {};
    for (int m = 0; m < NT; m++) {
        float v0 = vs[m * 33 + tx];
        float v1 = vs[m * 33 + tx + 16];
        #pragma unroll
        for (int i = 0; i < 7; i++) {
            float p = S[rn[i] * 99 + m];
            o0[i] = fmaf(p, v0, o0[i]);
            o1[i] = fmaf(p, v1, o1[i]);
        }
    }
    #pragma unroll
    for (int i = 0; i < 7; i++) {
        int n = ty + 16 * i;
        if (n < NT) {
            size_t ob = ((size_t)bwin * NT + n) * Cz + head * HD;
            g_ao[ob + tx]      = o0[i];
            g_ao[ob + tx + 16] = o1[i];
        }
    }
}

// ---------------- 6: window reverse + unshift + residual + LN2 ----------------
__global__ void k_rev_res_ln2(const float* __restrict__ g2, const float* __restrict__ b2) {
    int t = blockIdx.x;
    int ft = map_token(t);
    int c = threadIdx.x;
    float v = g_xw[(size_t)t * Cz + c] + g_xp[(size_t)ft * Cz + c];
    g_xres[(size_t)ft * Cz + c] = v;
    float m, inv;
    blockMeanVar(v, m, inv);
    g_ln2[(size_t)ft * Cz + c] = (v - m) * inv * g2[c] + b2[c];
}

// ---------------- 9: transpose out (B,D,H,W,C) -> (B,D,C,W,H) ----------------
__global__ void k_transpose_out(float* __restrict__ out) {
    __shared__ float tile[32][33];
    int bz = blockIdx.z;
    int bd = bz / Wz, w = bz % Wz;
    int h0 = blockIdx.x * 32, c0 = blockIdx.y * 32;
    #pragma unroll
    for (int j = 0; j < 32; j += 8) {
        int c = c0 + threadIdx.x;
        int h = h0 + threadIdx.y + j;
        if (h < Hz)
            tile[threadIdx.y + j][threadIdx.x] =
                g_y[(((size_t)bd * Hz + h) * Wz + w) * Cz + c];
    }
    __syncthreads();
    #pragma unroll
    for (int j = 0; j < 32; j += 8) {
        int h = h0 + threadIdx.x;
        int c = c0 + threadIdx.y + j;
        if (h < Hz)
            out[(((size_t)bd * Cz + c) * Wz + w) * Hz + h] =
                tile[threadIdx.x][threadIdx.y + j];
    }
}

// ---------------- launch ----------------
extern "C" void kernel_launch(void* const* d_in, const int* in_sizes, int n_in,
                              void* d_out, int out_size) {
    const float* x      = (const float*)d_in[0];
    const float* n1g    = (const float*)d_in[1];
    const float* n1b    = (const float*)d_in[2];
    const float* qkv_w  = (const float*)d_in[3];
    const float* rpb    = (const float*)d_in[4];
    const float* proj_w = (const float*)d_in[5];
    const float* proj_b = (const float*)d_in[6];
    const float* n2g    = (const float*)d_in[7];
    const float* n2b    = (const float*)d_in[8];
    const float* fc1_w  = (const float*)d_in[9];
    const float* fc1_b  = (const float*)d_in[10];
    const float* fc2_w  = (const float*)d_in[11];
    const float* fc2_b  = (const float*)d_in[12];
    float* out = (float*)d_out;

    void* p;
    cudaGetSymbolAddress(&p, g_xw);   float* xw   = (float*)p;
    cudaGetSymbolAddress(&p, g_qkv);  float* qkv  = (float*)p;
    cudaGetSymbolAddress(&p, g_ao);   float* ao   = (float*)p;
    cudaGetSymbolAddress(&p, g_xres); float* xres = (float*)p;
    cudaGetSymbolAddress(&p, g_ln2);  float* ln2  = (float*)p;
    cudaGetSymbolAddress(&p, g_hid);  float* hid  = (float*)p;
    cudaGetSymbolAddress(&p, g_y);    float* y    = (float*)p;

    dim3 tb(32, 8);
    dim3 tg(3, 8, Bz * Dz * Wz);

    // 1. transpose in
    k_transpose_in<<<tg, tb>>>(x);
    // 2. LN1 + shift + partition
    k_ln_part<<<TOK, 256>>>(n1g, n1b);
    // 3. qkv GEMM (tensor mma, no bias)
    k_gemm_mma<0, false, false><<<dim3((3 * Cz) / 128, TOK / 128), 256>>>(
        xw, qkv_w, nullptr, nullptr, qkv, TOK, 3 * Cz, Cz);
    // 4. attention
    const int ATTN_SMEM = (3 * NT * 33 + NT * 99) * 4;
    cudaFuncSetAttribute(k_attn, cudaFuncAttributeMaxDynamicSharedMemorySize, ATTN_SMEM);
    k_attn<<<dim3(HEADS, BW), 256, ATTN_SMEM>>>(rpb);
    // 5. proj GEMM (+bias) -> reuse g_xw
    k_gemm_mma<0, true, false><<<dim3(Cz / 128, TOK / 128), 256>>>(
        ao, proj_w, proj_b, nullptr, xw, TOK, Cz, Cz);
    // 6. reverse + residual + LN2
    k_rev_res_ln2<<<TOK, 256>>>(n2g, n2b);
    // 7. fc1 GEMM + GELU
    k_gemm_mma<1, true, false><<<dim3(HID / 128, TOK / 128), 256>>>(
        ln2, fc1_w, fc1_b, nullptr, hid, TOK, HID, Cz);
    // 8. fc2 GEMM + bias + residual
    k_gemm_mma<0, true, true><<<dim3(Cz / 128, TOK / 128), 256>>>(
        hid, fc2_w, fc2_b, xres, y, TOK, Cz, HID);
    // 9. transpose out
    k_transpose_out<<<tg, tb>>>(out);
}

// round 5
// speedup vs baseline: 2.8288x; 1.1767x over previous
#include <cuda_runtime.h>
#include <cuda_bf16.h>
#include <math.h>
#include <stdint.h>

// ---------------- problem constants ----------------
#define Bz 2
#define Dz 8
#define Cz 256
#define Wz 84
#define Hz 84
#define HEADS 8
#define HD 32
#define NT 98            // tokens per window (2*7*7)
#define NTP 112          // padded to 7 x 16
#define NW 576           // windows per batch (4*12*12)
#define BW (Bz*NW)       // 1152 window-batches
#define TOK (BW*NT)      // 112896 tokens
#define HID 1024

// ---------------- scratch (device globals; allocation-free) ----------------
__device__ float g_xp  [(size_t)TOK*Cz];   // shortcut, layout (B,D,H,W,C)
__device__ float g_xw  [(size_t)TOK*Cz];   // LN1+windowed tokens; reused for proj out
__device__ float g_qkv [(size_t)TOK*3*Cz];
__device__ float g_ao  [(size_t)TOK*Cz];   // attention output (windowed order)
__device__ float g_xres[(size_t)TOK*Cz];   // (B,D,H,W,C)
__device__ float g_ln2 [(size_t)TOK*Cz];
__device__ float g_hid [(size_t)TOK*HID];
__device__ float g_y   [(size_t)TOK*Cz];

// ---------------- helpers ----------------
__device__ __forceinline__ uint32_t smem_u32(const void* p) {
    uint32_t a;
    asm("{ .reg .u64 t; cvta.to.shared.u64 t, %1; cvt.u32.u64 %0, t; }" : "=r"(a) : "l"(p));
    return a;
}
__device__ __forceinline__ uint32_t pack2bf(float x, float y) {
    __nv_bfloat162 t = __floats2bfloat162_rn(x, y);
    return *(uint32_t*)&t;
}
__device__ __forceinline__ float bf_hi(float x) {
    return __bfloat162float(__float2bfloat16(x));
}
__device__ __forceinline__ void ldsm4(uint32_t addr, uint32_t& r0, uint32_t& r1,
                                      uint32_t& r2, uint32_t& r3) {
    asm volatile("ldmatrix.sync.aligned.m8n8.x4.shared.b16 {%0,%1,%2,%3}, [%4];"
                 : "=r"(r0), "=r"(r1), "=r"(r2), "=r"(r3) : "r"(addr));
}
__device__ __forceinline__ void mma_bf16(float* d, const uint32_t* a, const uint32_t* b) {
    asm volatile(
        "mma.sync.aligned.m16n8k16.row.col.f32.bf16.bf16.f32 "
        "{%0,%1,%2,%3}, {%4,%5,%6,%7}, {%8,%9}, {%0,%1,%2,%3};"
        : "+f"(d[0]), "+f"(d[1]), "+f"(d[2]), "+f"(d[3])
        : "r"(a[0]), "r"(a[1]), "r"(a[2]), "r"(a[3]), "r"(b[0]), "r"(b[1]));
}

// ---------------- 1: transpose in (B,D,C,W,H) -> (B,D,H,W,C) ----------------
__global__ void k_transpose_in(const float* __restrict__ x) {
    __shared__ float tile[32][33];
    int bz = blockIdx.z;
    int bd = bz / Wz, w = bz % Wz;
    int h0 = blockIdx.x * 32, c0 = blockIdx.y * 32;
    #pragma unroll
    for (int j = 0; j < 32; j += 8) {
        int c = c0 + threadIdx.y + j;
        int h = h0 + threadIdx.x;
        if (h < Hz)
            tile[threadIdx.y + j][threadIdx.x] =
                x[(((size_t)bd * Cz + c) * Wz + w) * Hz + h];
    }
    __syncthreads();
    #pragma unroll
    for (int j = 0; j < 32; j += 8) {
        int c = c0 + threadIdx.x;
        int h = h0 + threadIdx.y + j;
        if (h < Hz)
            g_xp[(((size_t)bd * Hz + h) * Wz + w) * Cz + c] =
                tile[threadIdx.x][threadIdx.y + j];
    }
}

__device__ __forceinline__ int map_token(int t) {
    int b   = t / (NW * NT);
    int rem = t % (NW * NT);
    int wi = rem / NT, n = rem % NT;
    int d2 = wi / 144, h2 = (wi / 12) % 12, w2 = wi % 12;
    int dd = n / 49, r = n % 49, hh = r / 7, ww = r % 7;
    int d = d2 * 2 + dd, h = h2 * 7 + hh, w = w2 * 7 + ww;
    int ds = (d + 1) & 7;
    int hs = h + 3; if (hs >= Hz) hs -= Hz;
    int ws = w + 3; if (ws >= Wz) ws -= Wz;
    return ((b * Dz + ds) * Hz + hs) * Wz + ws;
}

__device__ __forceinline__ void blockMeanVar(float v, float& mean, float& invstd) {
    __shared__ float sbuf[16];
    float s1 = v, s2 = v * v;
    #pragma unroll
    for (int o = 16; o; o >>= 1) {
        s1 += __shfl_down_sync(0xffffffffu, s1, o);
        s2 += __shfl_down_sync(0xffffffffu, s2, o);
    }
    int wp = threadIdx.x >> 5, ln = threadIdx.x & 31;
    if (!ln) { sbuf[wp] = s1; sbuf[8 + wp] = s2; }
    __syncthreads();
    float m = 0.f, q = 0.f;
    #pragma unroll
    for (int i = 0; i < 8; i++) { m += sbuf[i]; q += sbuf[8 + i]; }
    m *= (1.f / Cz);
    q = q * (1.f / Cz) - m * m;
    mean = m;
    invstd = rsqrtf(q + 1e-5f);
}

// ---------------- 2: LN1 + shift + window partition ----------------
__global__ void k_ln_part(const float* __restrict__ g, const float* __restrict__ bta) {
    int t = blockIdx.x;
    int srct = map_token(t);
    int c = threadIdx.x;
    float v = g_xp[(size_t)srct * Cz + c];
    float m, inv;
    blockMeanVar(v, m, inv);
    g_xw[(size_t)t * Cz + c] = (v - m) * inv * g[c] + bta[c];
}

// ---------------- mma.sync split-bf16 GEMM: out[M,N] = A[M,K] @ Wt[N,K]^T ----
#define PADK 40
template <int ACT, bool HAS_BIAS, bool HAS_RES>
__global__ __launch_bounds__(256, 2) void k_gemm_mma(
    const float* __restrict__ A, const float* __restrict__ Wt,
    const float* __restrict__ bias, const float* __restrict__ res,
    float* __restrict__ out, int M, int N, int K) {
    __shared__ __nv_bfloat16 sA[2][128 * PADK];   // [hi/lo]
    __shared__ __nv_bfloat16 sB[2][128 * PADK];
    int tid = threadIdx.x, lane = tid & 31, wid = tid >> 5;
    int bm = blockIdx.y * 128, bn = blockIdx.x * 128;
    int wm = (wid & 1) * 64, wn = (wid >> 1) * 32;

    uint32_t baseAH = smem_u32(sA[0]), baseAL = smem_u32(sA[1]);
    uint32_t baseBH = smem_u32(sB[0]), baseBL = smem_u32(sB[1]);

    int aRow = wm + (lane & 15);
    int aCol = (lane >> 4) * 8;
    int bRow = wn + ((lane >> 4) << 3) + (lane & 7);
    int bCol = ((lane >> 3) & 1) * 8;

    float acc[4][4][4];
    #pragma unroll
    for (int i = 0; i < 4; i++)
        #pragma unroll
        for (int j = 0; j < 4; j++)
            #pragma unroll
            for (int c = 0; c < 4; c++) acc[i][j][c] = 0.f;

    for (int k0c = 0; k0c < K; k0c += 32) {
        if (k0c) __syncthreads();
        #pragma unroll
        for (int it = 0; it < 4; it++) {
            int idx = it * 256 + tid;
            int row = idx >> 3, c4 = (idx & 7) << 2;
            float4 a = *(const float4*)(A + (size_t)(bm + row) * K + k0c + c4);
            float4 b = *(const float4*)(Wt + (size_t)(bn + row) * K + k0c + c4);
            int so = row * PADK + c4;
            float hx, hy, hz, hw;
            hx = bf_hi(a.x); hy = bf_hi(a.y); hz = bf_hi(a.z); hw = bf_hi(a.w);
            *(uint2*)&sA[0][so] = make_uint2(pack2bf(a.x, a.y), pack2bf(a.z, a.w));
            *(uint2*)&sA[1][so] = make_uint2(pack2bf(a.x - hx, a.y - hy),
                                             pack2bf(a.z - hz, a.w - hw));
            hx = bf_hi(b.x); hy = bf_hi(b.y); hz = bf_hi(b.z); hw = bf_hi(b.w);
            *(uint2*)&sB[0][so] = make_uint2(pack2bf(b.x, b.y), pack2bf(b.z, b.w));
            *(uint2*)&sB[1][so] = make_uint2(pack2bf(b.x - hx, b.y - hy),
                                             pack2bf(b.z - hz, b.w - hw));
        }
        __syncthreads();
        #pragma unroll
        for (int kk = 0; kk < 2; kk++) {
            int k0 = kk * 16;
            uint32_t aH[4][4], aL[4][4], bb[8];
            #pragma unroll
            for (int mi = 0; mi < 4; mi++) {
                uint32_t off = (uint32_t)(((aRow + mi * 16) * PADK + k0 + aCol) * 2);
                ldsm4(baseAH + off, aH[mi][0], aH[mi][1], aH[mi][2], aH[mi][3]);
                ldsm4(baseAL + off, aL[mi][0], aL[mi][1], aL[mi][2], aL[mi][3]);
            }
            #pragma unroll
            for (int p = 0; p < 2; p++) {
                uint32_t off = (uint32_t)(((bRow + p * 16) * PADK + k0 + bCol) * 2);
                ldsm4(baseBH + off, bb[p * 4 + 0], bb[p * 4 + 1], bb[p * 4 + 2], bb[p * 4 + 3]);
            }
            #pragma unroll
            for (int mi = 0; mi < 4; mi++)
                #pragma unroll
                for (int ni = 0; ni < 4; ni++)
                    mma_bf16(acc[mi][ni], aH[mi], &bb[ni * 2]);
            #pragma unroll
            for (int mi = 0; mi < 4; mi++)
                #pragma unroll
                for (int ni = 0; ni < 4; ni++)
                    mma_bf16(acc[mi][ni], aL[mi], &bb[ni * 2]);
            #pragma unroll
            for (int p = 0; p < 2; p++) {
                uint32_t off = (uint32_t)(((bRow + p * 16) * PADK + k0 + bCol) * 2);
                ldsm4(baseBL + off, bb[p * 4 + 0], bb[p * 4 + 1], bb[p * 4 + 2], bb[p * 4 + 3]);
            }
            #pragma unroll
            for (int mi = 0; mi < 4; mi++)
                #pragma unroll
                for (int ni = 0; ni < 4; ni++)
                    mma_bf16(acc[mi][ni], aH[mi], &bb[ni * 2]);
        }
    }

    int orow = lane >> 2, ocol = (lane & 3) * 2;
    #pragma unroll
    for (int mi = 0; mi < 4; mi++) {
        int m0 = bm + wm + mi * 16;
        #pragma unroll
        for (int ni = 0; ni < 4; ni++) {
            int n = bn + wn + ni * 8 + ocol;
            float bi0 = 0.f, bi1 = 0.f;
            if (HAS_BIAS) { bi0 = bias[n]; bi1 = bias[n + 1]; }
            #pragma unroll
            for (int half = 0; half < 2; half++) {
                int m = m0 + orow + half * 8;
                float v0 = acc[mi][ni][half * 2 + 0] + bi0;
                float v1 = acc[mi][ni][half * 2 + 1] + bi1;
                if (ACT == 1) {
                    v0 = 0.5f * v0 * (1.f + erff(v0 * 0.70710678118654752f));
                    v1 = 0.5f * v1 * (1.f + erff(v1 * 0.70710678118654752f));
                }
                if (HAS_RES) {
                    const float2 r2 = *(const float2*)(res + (size_t)m * N + n);
                    v0 += r2.x; v1 += r2.y;
                }
                *(float2*)(out + (size_t)m * N + n) = make_float2(v0, v1);
            }
        }
    }
}

// ---------------- 4: tensor-core attention per (head, window) ----------------
// 7 warps; warp w owns m16 tile rows [16w, 16w+16). S kept entirely in regs;
// c-frag(S) layout == a-frag(P) layout, so softmax+bias also in regs.
// smem halves: sQh 0, sQl 4480, sKh 8960, sKl 13440, sVth 17920 (32x120),
// sVtl 21760 (32x120). Total 25600 halves = 51200 B.
#define ATTN_SMEM_TC 51200
__global__ __launch_bounds__(224, 2) void k_attn_tc(const float* __restrict__ rpb) {
    extern __shared__ __nv_bfloat16 asm_[];
    __nv_bfloat16* sQh = asm_;
    __nv_bfloat16* sQl = asm_ + 4480;
    __nv_bfloat16* sKh = asm_ + 8960;
    __nv_bfloat16* sKl = asm_ + 13440;
    __nv_bfloat16* sVth = asm_ + 17920;
    __nv_bfloat16* sVtl = asm_ + 21760;
    __shared__ unsigned char ddv[NTP], hhv[NTP], wwv[NTP];
    __shared__ int regn[NTP];

    int head = blockIdx.x, bwin = blockIdx.y;
    int tid = threadIdx.x, lane = tid & 31, wid = tid >> 5;
    const float scale = 0.17677669529663687f;

    // zero-fill all smem (pad rows must be 0): 25600 halves = 12800 u32
    uint32_t* z = (uint32_t*)asm_;
    for (int i = tid; i < 12800; i += 224) z[i] = 0u;
    if (tid < NTP) {
        if (tid < NT) {
            int wi = bwin % NW;
            int dd = tid / 49, r = tid % 49, hh = r / 7, ww = r % 7;
            ddv[tid] = (unsigned char)dd; hhv[tid] = (unsigned char)hh; wwv[tid] = (unsigned char)ww;
            int gd = (wi / 144) * 2 + dd;
            int gh = ((wi / 12) % 12) * 7 + hh;
            int gw = (wi % 12) * 7 + ww;
            int rd = gd < 6  ? 0 : (gd < 7  ? 1 : 2);
            int rh = gh < 77 ? 0 : (gh < 81 ? 1 : 2);
            int rw = gw < 77 ? 0 : (gw < 81 ? 1 : 2);
            regn[tid] = rd * 9 + rh * 3 + rw;
        } else {
            ddv[tid] = hhv[tid] = wwv[tid] = 0; regn[tid] = -1;
        }
    }
    __syncthreads();

    // load Q,K (hi/lo, scaled Q) and V transposed
    size_t base = (size_t)bwin * NT * (3 * Cz) + head * HD;
    for (int i = tid; i < NT * HD; i += 224) {
        int n = i >> 5, j = i & 31;
        const float* p = g_qkv + base + (size_t)n * (3 * Cz) + j;
        float q = p[0] * scale, k = p[Cz], v = p[2 * Cz];
        float qh = bf_hi(q), kh = bf_hi(k), vh = bf_hi(v);
        sQh[n * 40 + j] = __float2bfloat16(q);
        sQl[n * 40 + j] = __float2bfloat16(q - qh);
        sKh[n * 40 + j] = __float2bfloat16(k);
        sKl[n * 40 + j] = __float2bfloat16(k - kh);
        sVth[j * 120 + n] = __float2bfloat16(v);
        sVtl[j * 120 + n] = __float2bfloat16(v - vh);
    }
    __syncthreads();

    int wm = wid * 16;
    uint32_t bQh = smem_u32(sQh), bQl = smem_u32(sQl);
    uint32_t bKh = smem_u32(sKh), bKl = smem_u32(sKl);
    uint32_t bVh = smem_u32(sVth), bVl = smem_u32(sVtl);

    int aRow = wm + (lane & 15);
    int aCol = (lane >> 4) * 8;
    int bR = ((lane >> 4) << 3) + (lane & 7);
    int bCol = ((lane >> 3) & 1) * 8;

    // S accum: sacc[nt][0..1] = row r0 cols {2c,2c+1}; [2..3] = row r0+8
    float sacc[14][4];
    #pragma unroll
    for (int t = 0; t < 14; t++)
        #pragma unroll
        for (int e = 0; e < 4; e++) sacc[t][e] = 0.f;

    #pragma unroll
    for (int kk = 0; kk < 2; kk++) {
        int k0 = kk * 16;
        uint32_t aH[4], aL[4], bbH[4], bbL[4];
        uint32_t aoff = (uint32_t)((aRow * 40 + k0 + aCol) * 2);
        ldsm4(bQh + aoff, aH[0], aH[1], aH[2], aH[3]);
        ldsm4(bQl + aoff, aL[0], aL[1], aL[2], aL[3]);
        #pragma unroll
        for (int nt = 0; nt < 7; nt++) {
            uint32_t boff = (uint32_t)(((nt * 16 + bR) * 40 + k0 + bCol) * 2);
            ldsm4(bKh + boff, bbH[0], bbH[1], bbH[2], bbH[3]);
            ldsm4(bKl + boff, bbL[0], bbL[1], bbL[2], bbL[3]);
            mma_bf16(sacc[nt * 2 + 0], aH, &bbH[0]);
            mma_bf16(sacc[nt * 2 + 1], aH, &bbH[2]);
            mma_bf16(sacc[nt * 2 + 0], aH, &bbL[0]);
            mma_bf16(sacc[nt * 2 + 1], aH, &bbL[2]);
            mma_bf16(sacc[nt * 2 + 0], aL, &bbH[0]);
            mma_bf16(sacc[nt * 2 + 1], aL, &bbH[2]);
        }
    }

    // bias + mask (in regs)
    int r0 = wm + (lane >> 2);
    int cbase = (lane & 3) * 2;
    #pragma unroll
    for (int h = 0; h < 2; h++) {
        int r = r0 + h * 8;
        if (r < NT) {
            int dn = ddv[r], hn = hhv[r], wn = wwv[r], rg = regn[r];
            #pragma unroll
            for (int t = 0; t < 14; t++) {
                #pragma unroll
                for (int e = 0; e < 2; e++) {
                    int c = t * 8 + cbase + e;
                    if (c < NT) {
                        int idx = (dn - (int)ddv[c] + 1) * 169
                                + (hn - (int)hhv[c] + 6) * 13
                                + (wn - (int)wwv[c] + 6);
                        float mk = (rg != regn[c]) ? -100.f : 0.f;
                        sacc[t][h * 2 + e] += rpb[idx * HEADS + head] + mk;
                    } else {
                        sacc[t][h * 2 + e] = -1e30f;
                    }
                }
            }
        }
    }

    // softmax in regs (row = quad of lanes; shfl_xor 1,2)
    #pragma unroll
    for (int h = 0; h < 2; h++) {
        float mx = -1e30f;
        #pragma unroll
        for (int t = 0; t < 14; t++) {
            mx = fmaxf(mx, sacc[t][h * 2 + 0]);
            mx = fmaxf(mx, sacc[t][h * 2 + 1]);
        }
        mx = fmaxf(mx, __shfl_xor_sync(0xffffffffu, mx, 1));
        mx = fmaxf(mx, __shfl_xor_sync(0xffffffffu, mx, 2));
        float sum = 0.f;
        #pragma unroll
        for (int t = 0; t < 14; t++) {
            #pragma unroll
            for (int e = 0; e < 2; e++) {
                float v = __expf(sacc[t][h * 2 + e] - mx);
                sacc[t][h * 2 + e] = v;
                sum += v;
            }
        }
        sum += __shfl_xor_sync(0xffffffffu, sum, 1);
        sum += __shfl_xor_sync(0xffffffffu, sum, 2);
        float inv = 1.f / sum;
        #pragma unroll
        for (int t = 0; t < 14; t++) {
            sacc[t][h * 2 + 0] *= inv;
            sacc[t][h * 2 + 1] *= inv;
        }
    }

    // P @ V : P a-frags built from sacc (c-frag(2j,2j+1) == a-frag(j))
    float oacc[4][4];
    #pragma unroll
    for (int i = 0; i < 4; i++)
        #pragma unroll
        for (int e = 0; e < 4; e++) oacc[i][e] = 0.f;

    #pragma unroll
    for (int j = 0; j < 7; j++) {
        uint32_t aH[4], aL[4];
        #pragma unroll
        for (int q = 0; q < 2; q++) {      // q=0 -> tile 2j (k0-7), q=1 -> 2j+1 (k8-15)
            float p0 = sacc[2 * j + q][0], p1 = sacc[2 * j + q][1];
            float p2 = sacc[2 * j + q][2], p3 = sacc[2 * j + q][3];
            aH[q * 2 + 0] = pack2bf(p0, p1);
            aH[q * 2 + 1] = pack2bf(p2, p3);
            aL[q * 2 + 0] = pack2bf(p0 - bf_hi(p0), p1 - bf_hi(p1));
            aL[q * 2 + 1] = pack2bf(p2 - bf_hi(p2), p3 - bf_hi(p3));
        }
        uint32_t af[4] = { aH[0], aH[1], aH[2], aH[3] };
        uint32_t alf[4] = { aL[0], aL[1], aL[2], aL[3] };
        int k0 = j * 16;
        #pragma unroll
        for (int ng = 0; ng < 2; ng++) {
            uint32_t bbH[4], bbL[4];
            uint32_t boff = (uint32_t)(((ng * 16 + bR) * 120 + k0 + bCol) * 2);
            ldsm4(bVh + boff, bbH[0], bbH[1], bbH[2], bbH[3]);
            ldsm4(bVl + boff, bbL[0], bbL[1], bbL[2], bbL[3]);
            mma_bf16(oacc[ng * 2 + 0], af, &bbH[0]);
            mma_bf16(oacc[ng * 2 + 1], af, &bbH[2]);
            mma_bf16(oacc[ng * 2 + 0], af, &bbL[0]);
            mma_bf16(oacc[ng * 2 + 1], af, &bbL[2]);
            mma_bf16(oacc[ng * 2 + 0], alf, &bbH[0]);
            mma_bf16(oacc[ng * 2 + 1], alf, &bbH[2]);
        }
    }

    // epilogue
    #pragma unroll
    for (int h = 0; h < 2; h++) {
        int r = r0 + h * 8;
        if (r < NT) {
            size_t ob = ((size_t)bwin * NT + r) * Cz + head * HD;
            #pragma unroll
            for (int nt = 0; nt < 4; nt++) {
                int c = nt * 8 + cbase;
                *(float2*)(g_ao + ob + c) =
                    make_float2(oacc[nt][h * 2 + 0], oacc[nt][h * 2 + 1]);
            }
        }
    }
}

// ---------------- 6: window reverse + unshift + residual + LN2 ----------------
__global__ void k_rev_res_ln2(const float* __restrict__ g2, const float* __restrict__ b2) {
    int t = blockIdx.x;
    int ft = map_token(t);
    int c = threadIdx.x;
    float v = g_xw[(size_t)t * Cz + c] + g_xp[(size_t)ft * Cz + c];
    g_xres[(size_t)ft * Cz + c] = v;
    float m, inv;
    blockMeanVar(v, m, inv);
    g_ln2[(size_t)ft * Cz + c] = (v - m) * inv * g2[c] + b2[c];
}

// ---------------- 9: transpose out (B,D,H,W,C) -> (B,D,C,W,H) ----------------
__global__ void k_transpose_out(float* __restrict__ out) {
    __shared__ float tile[32][33];
    int bz = blockIdx.z;
    int bd = bz / Wz, w = bz % Wz;
    int h0 = blockIdx.x * 32, c0 = blockIdx.y * 32;
    #pragma unroll
    for (int j = 0; j < 32; j += 8) {
        int c = c0 + threadIdx.x;
        int h = h0 + threadIdx.y + j;
        if (h < Hz)
            tile[threadIdx.y + j][threadIdx.x] =
                g_y[(((size_t)bd * Hz + h) * Wz + w) * Cz + c];
    }
    __syncthreads();
    #pragma unroll
    for (int j = 0; j < 32; j += 8) {
        int h = h0 + threadIdx.x;
        int c = c0 + threadIdx.y + j;
        if (h < Hz)
            out[(((size_t)bd * Cz + c) * Wz + w) * Hz + h] =
                tile[threadIdx.x][threadIdx.y + j];
    }
}

// ---------------- launch ----------------
extern "C" void kernel_launch(void* const* d_in, const int* in_sizes, int n_in,
                              void* d_out, int out_size) {
    const float* x      = (const float*)d_in[0];
    const float* n1g    = (const float*)d_in[1];
    const float* n1b    = (const float*)d_in[2];
    const float* qkv_w  = (const float*)d_in[3];
    const float* rpb    = (const float*)d_in[4];
    const float* proj_w = (const float*)d_in[5];
    const float* proj_b = (const float*)d_in[6];
    const float* n2g    = (const float*)d_in[7];
    const float* n2b    = (const float*)d_in[8];
    const float* fc1_w  = (const float*)d_in[9];
    const float* fc1_b  = (const float*)d_in[10];
    const float* fc2_w  = (const float*)d_in[11];
    const float* fc2_b  = (const float*)d_in[12];
    float* out = (float*)d_out;

    void* p;
    cudaGetSymbolAddress(&p, g_xw);   float* xw   = (float*)p;
    cudaGetSymbolAddress(&p, g_qkv);  float* qkv  = (float*)p;
    cudaGetSymbolAddress(&p, g_ao);   float* ao   = (float*)p;
    cudaGetSymbolAddress(&p, g_xres); float* xres = (float*)p;
    cudaGetSymbolAddress(&p, g_ln2);  float* ln2  = (float*)p;
    cudaGetSymbolAddress(&p, g_hid);  float* hid  = (float*)p;
    cudaGetSymbolAddress(&p, g_y);    float* y    = (float*)p;

    cudaFuncSetAttribute(k_attn_tc, cudaFuncAttributeMaxDynamicSharedMemorySize, ATTN_SMEM_TC);

    dim3 tb(32, 8);
    dim3 tg(3, 8, Bz * Dz * Wz);

    // 1. transpose in
    k_transpose_in<<<tg, tb>>>(x);
    // 2. LN1 + shift + partition
    k_ln_part<<<TOK, 256>>>(n1g, n1b);
    // 3. qkv GEMM
    k_gemm_mma<0, false, false><<<dim3((3 * Cz) / 128, TOK / 128), 256>>>(
        xw, qkv_w, nullptr, nullptr, qkv, TOK, 3 * Cz, Cz);
    // 4. attention (tensor cores)
    k_attn_tc<<<dim3(HEADS, BW), 224, ATTN_SMEM_TC>>>(rpb);
    // 5. proj GEMM (+bias) -> reuse g_xw
    k_gemm_mma<0, true, false><<<dim3(Cz / 128, TOK / 128), 256>>>(
        ao, proj_w, proj_b, nullptr, xw, TOK, Cz, Cz);
    // 6. reverse + residual + LN2
    k_rev_res_ln2<<<TOK, 256>>>(n2g, n2b);
    // 7. fc1 GEMM + GELU
    k_gemm_mma<1, true, false><<<dim3(HID / 128, TOK / 128), 256>>>(
        ln2, fc1_w, fc1_b, nullptr, hid, TOK, HID, Cz);
    // 8. fc2 GEMM + bias + residual
    k_gemm_mma<0, true, true><<<dim3(Cz / 128, TOK / 128), 256>>>(
        hid, fc2_w, fc2_b, xres, y, TOK, Cz, HID);
    // 9. transpose out
    k_transpose_out<<<tg, tb>>>(out);
}

// round 6
// speedup vs baseline: 2.8369x; 1.0029x over previous
#include <cuda_runtime.h>
#include <cuda_bf16.h>
#include <math.h>
#include <stdint.h>

// ---------------- problem constants ----------------
#define Bz 2
#define Dz 8
#define Cz 256
#define Wz 84
#define Hz 84
#define HEADS 8
#define HD 32
#define NT 98            // tokens per window (2*7*7)
#define NTP 112          // padded to 7 x 16
#define NW 576           // windows per batch (4*12*12)
#define BW (Bz*NW)       // 1152 window-batches
#define TOK (BW*NT)      // 112896 tokens
#define HID 1024

// ---------------- scratch (device globals; allocation-free) ----------------
__device__ __align__(256) float g_xp  [(size_t)TOK*Cz];   // shortcut (B,D,H,W,C)
__device__ __align__(256) float g_qkv [(size_t)TOK*3*Cz];
__device__ __align__(256) float g_po  [(size_t)TOK*Cz];   // proj output (windowed order)
__device__ __align__(256) float g_xres[(size_t)TOK*Cz];   // (B,D,H,W,C)
__device__ __align__(256) float g_y   [(size_t)TOK*Cz];
// split bf16 activation planes
__device__ __align__(256) __nv_bfloat16 g_xwh[(size_t)TOK*Cz], g_xwl[(size_t)TOK*Cz];
__device__ __align__(256) __nv_bfloat16 g_aoh[(size_t)TOK*Cz], g_aol[(size_t)TOK*Cz];
__device__ __align__(256) __nv_bfloat16 g_l2h[(size_t)TOK*Cz], g_l2l[(size_t)TOK*Cz];
__device__ __align__(256) __nv_bfloat16 g_hih[(size_t)TOK*HID], g_hil[(size_t)TOK*HID];
// split bf16 weights
__device__ __align__(256) __nv_bfloat16 g_wqh[3*Cz*Cz], g_wql[3*Cz*Cz];
__device__ __align__(256) __nv_bfloat16 g_wph[Cz*Cz],   g_wpl[Cz*Cz];
__device__ __align__(256) __nv_bfloat16 g_w1h[HID*Cz],  g_w1l[HID*Cz];
__device__ __align__(256) __nv_bfloat16 g_w2h[Cz*HID],  g_w2l[Cz*HID];

// ---------------- helpers ----------------
__device__ __forceinline__ uint32_t smem_u32(const void* p) {
    uint32_t a;
    asm("{ .reg .u64 t; cvta.to.shared.u64 t, %1; cvt.u32.u64 %0, t; }" : "=r"(a) : "l"(p));
    return a;
}
__device__ __forceinline__ uint32_t pack2bf(float x, float y) {
    __nv_bfloat162 t = __floats2bfloat162_rn(x, y);
    return *(uint32_t*)&t;
}
__device__ __forceinline__ float bf_hi(float x) {
    return __bfloat162float(__float2bfloat16(x));
}
__device__ __forceinline__ void ldsm4(uint32_t addr, uint32_t& r0, uint32_t& r1,
                                      uint32_t& r2, uint32_t& r3) {
    asm volatile("ldmatrix.sync.aligned.m8n8.x4.shared.b16 {%0,%1,%2,%3}, [%4];"
                 : "=r"(r0), "=r"(r1), "=r"(r2), "=r"(r3) : "r"(addr));
}
__device__ __forceinline__ void mma_bf16(float* d, const uint32_t* a, const uint32_t* b) {
    asm volatile(
        "mma.sync.aligned.m16n8k16.row.col.f32.bf16.bf16.f32 "
        "{%0,%1,%2,%3}, {%4,%5,%6,%7}, {%8,%9}, {%0,%1,%2,%3};"
        : "+f"(d[0]), "+f"(d[1]), "+f"(d[2]), "+f"(d[3])
        : "r"(a[0]), "r"(a[1]), "r"(a[2]), "r"(a[3]), "r"(b[0]), "r"(b[1]));
}
__device__ __forceinline__ void cpasync16(uint32_t dst, const void* src) {
    asm volatile("cp.async.cg.shared.global [%0], [%1], 16;" :: "r"(dst), "l"(src));
}

// ---------------- 0: weight split ----------------
__global__ void k_wsplit(const float* __restrict__ src, __nv_bfloat16* __restrict__ hi,
                         __nv_bfloat16* __restrict__ lo, int n) {
    int i = blockIdx.x * 256 + threadIdx.x;
    if (i < n) {
        float v = src[i];
        float h = bf_hi(v);
        hi[i] = __float2bfloat16(v);
        lo[i] = __float2bfloat16(v - h);
    }
}

// ---------------- 1: transpose in (B,D,C,W,H) -> (B,D,H,W,C) ----------------
__global__ void k_transpose_in(const float* __restrict__ x) {
    __shared__ float tile[32][33];
    int bz = blockIdx.z;
    int bd = bz / Wz, w = bz % Wz;
    int h0 = blockIdx.x * 32, c0 = blockIdx.y * 32;
    #pragma unroll
    for (int j = 0; j < 32; j += 8) {
        int c = c0 + threadIdx.y + j;
        int h = h0 + threadIdx.x;
        if (h < Hz)
            tile[threadIdx.y + j][threadIdx.x] =
                x[(((size_t)bd * Cz + c) * Wz + w) * Hz + h];
    }
    __syncthreads();
    #pragma unroll
    for (int j = 0; j < 32; j += 8) {
        int c = c0 + threadIdx.x;
        int h = h0 + threadIdx.y + j;
        if (h < Hz)
            g_xp[(((size_t)bd * Hz + h) * Wz + w) * Cz + c] =
                tile[threadIdx.x][threadIdx.y + j];
    }
}

__device__ __forceinline__ int map_token(int t) {
    int b   = t / (NW * NT);
    int rem = t % (NW * NT);
    int wi = rem / NT, n = rem % NT;
    int d2 = wi / 144, h2 = (wi / 12) % 12, w2 = wi % 12;
    int dd = n / 49, r = n % 49, hh = r / 7, ww = r % 7;
    int d = d2 * 2 + dd, h = h2 * 7 + hh, w = w2 * 7 + ww;
    int ds = (d + 1) & 7;
    int hs = h + 3; if (hs >= Hz) hs -= Hz;
    int ws = w + 3; if (ws >= Wz) ws -= Wz;
    return ((b * Dz + ds) * Hz + hs) * Wz + ws;
}

__device__ __forceinline__ void blockMeanVar(float v, float& mean, float& invstd) {
    __shared__ float sbuf[16];
    float s1 = v, s2 = v * v;
    #pragma unroll
    for (int o = 16; o; o >>= 1) {
        s1 += __shfl_down_sync(0xffffffffu, s1, o);
        s2 += __shfl_down_sync(0xffffffffu, s2, o);
    }
    int wp = threadIdx.x >> 5, ln = threadIdx.x & 31;
    if (!ln) { sbuf[wp] = s1; sbuf[8 + wp] = s2; }
    __syncthreads();
    float m = 0.f, q = 0.f;
    #pragma unroll
    for (int i = 0; i < 8; i++) { m += sbuf[i]; q += sbuf[8 + i]; }
    m *= (1.f / Cz);
    q = q * (1.f / Cz) - m * m;
    mean = m;
    invstd = rsqrtf(q + 1e-5f);
}

// ---------------- 2: LN1 + shift + partition -> split bf16 ----------------
__global__ void k_ln_part(const float* __restrict__ g, const float* __restrict__ bta) {
    int t = blockIdx.x;
    int srct = map_token(t);
    int c = threadIdx.x;
    float v = g_xp[(size_t)srct * Cz + c];
    float m, inv;
    blockMeanVar(v, m, inv);
    float o = (v - m) * inv * g[c] + bta[c];
    float oh = bf_hi(o);
    g_xwh[(size_t)t * Cz + c] = __float2bfloat16(o);
    g_xwl[(size_t)t * Cz + c] = __float2bfloat16(o - oh);
}

// ---------------- GEMM: out[M,N] = A[M,K] @ Wt[N,K]^T (split-bf16, cp.async) --
// operands pre-split planar bf16 (hi/lo). 128x128 tile, BK=32, 2-stage pipeline.
// smem per stage: 4 planes (AH, AL, BH, BL) of 128 x PADK halves.
#define PADK 40
#define PLANE_B (128 * PADK * 2)       // 10240 bytes
#define STAGE_B (4 * PLANE_B)          // 40960 bytes
#define GEMM_SMEM (2 * STAGE_B)        // 81920 bytes
template <int ACT, bool HAS_BIAS, bool HAS_RES, bool OSPLIT>
__global__ __launch_bounds__(256, 2) void k_gemm_bf(
    const __nv_bfloat16* __restrict__ Ah, const __nv_bfloat16* __restrict__ Al,
    const __nv_bfloat16* __restrict__ Bh, const __nv_bfloat16* __restrict__ Bl,
    const float* __restrict__ bias, const float* __restrict__ res,
    float* __restrict__ out,
    __nv_bfloat16* __restrict__ outh, __nv_bfloat16* __restrict__ outl,
    int M, int N, int K) {
    extern __shared__ __align__(16) unsigned char dsm[];
    uint32_t sbase = smem_u32(dsm);
    int tid = threadIdx.x, lane = tid & 31, wid = tid >> 5;
    int bm = blockIdx.y * 128, bn = blockIdx.x * 128;
    int wm = (wid & 1) * 64, wn = (wid >> 1) * 32;

    int aRow = wm + (lane & 15);
    int aCol = (lane >> 4) * 8;
    int bRow = wn + ((lane >> 4) << 3) + (lane & 7);
    int bCol = ((lane >> 3) & 1) * 8;

    float acc[4][4][4];
    #pragma unroll
    for (int i = 0; i < 4; i++)
        #pragma unroll
        for (int j = 0; j < 4; j++)
            #pragma unroll
            for (int c = 0; c < 4; c++) acc[i][j][c] = 0.f;

    const int nChunks = K >> 5;

    // ---- issue chunk ch into stage s ----
    #define ISSUE(ch, s) do {                                                   \
        int k0_ = (ch) << 5;                                                    \
        uint32_t sb_ = sbase + (s) * STAGE_B;                                   \
        _Pragma("unroll")                                                       \
        for (int q_ = 0; q_ < 2; q_++) {                                        \
            int j_ = q_ * 256 + tid;                                            \
            int row_ = j_ >> 2, c8_ = (j_ & 3) * 8;                             \
            uint32_t so_ = (uint32_t)((row_ * PADK + c8_) * 2);                 \
            size_t ga_ = (size_t)(bm + row_) * K + k0_ + c8_;                   \
            size_t gb_ = (size_t)(bn + row_) * K + k0_ + c8_;                   \
            cpasync16(sb_ + 0 * PLANE_B + so_, Ah + ga_);                       \
            cpasync16(sb_ + 1 * PLANE_B + so_, Al + ga_);                       \
            cpasync16(sb_ + 2 * PLANE_B + so_, Bh + gb_);                       \
            cpasync16(sb_ + 3 * PLANE_B + so_, Bl + gb_);                       \
        }                                                                       \
        asm volatile("cp.async.commit_group;");                                 \
    } while (0)

    ISSUE(0, 0);
    for (int ch = 0; ch < nChunks; ch++) {
        int s = ch & 1;
        if (ch + 1 < nChunks) {
            ISSUE(ch + 1, (ch + 1) & 1);
            asm volatile("cp.async.wait_group 1;");
        } else {
            asm volatile("cp.async.wait_group 0;");
        }
        __syncthreads();

        uint32_t baseAH = sbase + s * STAGE_B;
        uint32_t baseAL = baseAH + PLANE_B;
        uint32_t baseBH = baseAH + 2 * PLANE_B;
        uint32_t baseBL = baseAH + 3 * PLANE_B;

        #pragma unroll
        for (int kk = 0; kk < 2; kk++) {
            int k0 = kk * 16;
            uint32_t aH[4][4], aL[4][4], bb[8];
            #pragma unroll
            for (int mi = 0; mi < 4; mi++) {
                uint32_t off = (uint32_t)(((aRow + mi * 16) * PADK + k0 + aCol) * 2);
                ldsm4(baseAH + off, aH[mi][0], aH[mi][1], aH[mi][2], aH[mi][3]);
                ldsm4(baseAL + off, aL[mi][0], aL[mi][1], aL[mi][2], aL[mi][3]);
            }
            #pragma unroll
            for (int p = 0; p < 2; p++) {
                uint32_t off = (uint32_t)(((bRow + p * 16) * PADK + k0 + bCol) * 2);
                ldsm4(baseBH + off, bb[p * 4 + 0], bb[p * 4 + 1], bb[p * 4 + 2], bb[p * 4 + 3]);
            }
            #pragma unroll
            for (int mi = 0; mi < 4; mi++)
                #pragma unroll
                for (int ni = 0; ni < 4; ni++)
                    mma_bf16(acc[mi][ni], aH[mi], &bb[ni * 2]);
            #pragma unroll
            for (int mi = 0; mi < 4; mi++)
                #pragma unroll
                for (int ni = 0; ni < 4; ni++)
                    mma_bf16(acc[mi][ni], aL[mi], &bb[ni * 2]);
            #pragma unroll
            for (int p = 0; p < 2; p++) {
                uint32_t off = (uint32_t)(((bRow + p * 16) * PADK + k0 + bCol) * 2);
                ldsm4(baseBL + off, bb[p * 4 + 0], bb[p * 4 + 1], bb[p * 4 + 2], bb[p * 4 + 3]);
            }
            #pragma unroll
            for (int mi = 0; mi < 4; mi++)
                #pragma unroll
                for (int ni = 0; ni < 4; ni++)
                    mma_bf16(acc[mi][ni], aH[mi], &bb[ni * 2]);
        }
        __syncthreads();
    }
    #undef ISSUE

    int orow = lane >> 2, ocol = (lane & 3) * 2;
    #pragma unroll
    for (int mi = 0; mi < 4; mi++) {
        int m0 = bm + wm + mi * 16;
        #pragma unroll
        for (int ni = 0; ni < 4; ni++) {
            int n = bn + wn + ni * 8 + ocol;
            float bi0 = 0.f, bi1 = 0.f;
            if (HAS_BIAS) { bi0 = bias[n]; bi1 = bias[n + 1]; }
            #pragma unroll
            for (int half = 0; half < 2; half++) {
                int m = m0 + orow + half * 8;
                float v0 = acc[mi][ni][half * 2 + 0] + bi0;
                float v1 = acc[mi][ni][half * 2 + 1] + bi1;
                if (ACT == 1) {
                    v0 = 0.5f * v0 * (1.f + erff(v0 * 0.70710678118654752f));
                    v1 = 0.5f * v1 * (1.f + erff(v1 * 0.70710678118654752f));
                }
                if (HAS_RES) {
                    const float2 r2 = *(const float2*)(res + (size_t)m * N + n);
                    v0 += r2.x; v1 += r2.y;
                }
                if (OSPLIT) {
                    *(uint32_t*)(outh + (size_t)m * N + n) = pack2bf(v0, v1);
                    *(uint32_t*)(outl + (size_t)m * N + n) =
                        pack2bf(v0 - bf_hi(v0), v1 - bf_hi(v1));
                } else {
                    *(float2*)(out + (size_t)m * N + n) = make_float2(v0, v1);
                }
            }
        }
    }
}

// ---------------- 4: tensor-core attention per (head, window) ----------------
#define ATTN_SMEM_TC 51200
__global__ __launch_bounds__(224, 2) void k_attn_tc(const float* __restrict__ rpb) {
    extern __shared__ __nv_bfloat16 asm_[];
    __nv_bfloat16* sQh = asm_;
    __nv_bfloat16* sQl = asm_ + 4480;
    __nv_bfloat16* sKh = asm_ + 8960;
    __nv_bfloat16* sKl = asm_ + 13440;
    __nv_bfloat16* sVth = asm_ + 17920;
    __nv_bfloat16* sVtl = asm_ + 21760;
    __shared__ unsigned char ddv[NTP], hhv[NTP], wwv[NTP];
    __shared__ int regn[NTP];

    int head = blockIdx.x, bwin = blockIdx.y;
    int tid = threadIdx.x, lane = tid & 31, wid = tid >> 5;
    const float scale = 0.17677669529663687f;

    uint32_t* z = (uint32_t*)asm_;
    for (int i = tid; i < 12800; i += 224) z[i] = 0u;
    if (tid < NTP) {
        if (tid < NT) {
            int wi = bwin % NW;
            int dd = tid / 49, r = tid % 49, hh = r / 7, ww = r % 7;
            ddv[tid] = (unsigned char)dd; hhv[tid] = (unsigned char)hh; wwv[tid] = (unsigned char)ww;
            int gd = (wi / 144) * 2 + dd;
            int gh = ((wi / 12) % 12) * 7 + hh;
            int gw = (wi % 12) * 7 + ww;
            int rd = gd < 6  ? 0 : (gd < 7  ? 1 : 2);
            int rh = gh < 77 ? 0 : (gh < 81 ? 1 : 2);
            int rw = gw < 77 ? 0 : (gw < 81 ? 1 : 2);
            regn[tid] = rd * 9 + rh * 3 + rw;
        } else {
            ddv[tid] = hhv[tid] = wwv[tid] = 0; regn[tid] = -1;
        }
    }
    __syncthreads();

    size_t base = (size_t)bwin * NT * (3 * Cz) + head * HD;
    for (int i = tid; i < NT * HD; i += 224) {
        int n = i >> 5, j = i & 31;
        const float* p = g_qkv + base + (size_t)n * (3 * Cz) + j;
        float q = p[0] * scale, k = p[Cz], v = p[2 * Cz];
        float qh = bf_hi(q), kh = bf_hi(k), vh = bf_hi(v);
        sQh[n * 40 + j] = __float2bfloat16(q);
        sQl[n * 40 + j] = __float2bfloat16(q - qh);
        sKh[n * 40 + j] = __float2bfloat16(k);
        sKl[n * 40 + j] = __float2bfloat16(k - kh);
        sVth[j * 120 + n] = __float2bfloat16(v);
        sVtl[j * 120 + n] = __float2bfloat16(v - vh);
    }
    __syncthreads();

    int wm = wid * 16;
    uint32_t bQh = smem_u32(sQh), bQl = smem_u32(sQl);
    uint32_t bKh = smem_u32(sKh), bKl = smem_u32(sKl);
    uint32_t bVh = smem_u32(sVth), bVl = smem_u32(sVtl);

    int aRow = wm + (lane & 15);
    int aCol = (lane >> 4) * 8;
    int bR = ((lane >> 4) << 3) + (lane & 7);
    int bCol = ((lane >> 3) & 1) * 8;

    float sacc[14][4];
    #pragma unroll
    for (int t = 0; t < 14; t++)
        #pragma unroll
        for (int e = 0; e < 4; e++) sacc[t][e] = 0.f;

    #pragma unroll
    for (int kk = 0; kk < 2; kk++) {
        int k0 = kk * 16;
        uint32_t aH[4], aL[4], bbH[4], bbL[4];
        uint32_t aoff = (uint32_t)((aRow * 40 + k0 + aCol) * 2);
        ldsm4(bQh + aoff, aH[0], aH[1], aH[2], aH[3]);
        ldsm4(bQl + aoff, aL[0], aL[1], aL[2], aL[3]);
        #pragma unroll
        for (int nt = 0; nt < 7; nt++) {
            uint32_t boff = (uint32_t)(((nt * 16 + bR) * 40 + k0 + bCol) * 2);
            ldsm4(bKh + boff, bbH[0], bbH[1], bbH[2], bbH[3]);
            ldsm4(bKl + boff, bbL[0], bbL[1], bbL[2], bbL[3]);
            mma_bf16(sacc[nt * 2 + 0], aH, &bbH[0]);
            mma_bf16(sacc[nt * 2 + 1], aH, &bbH[2]);
            mma_bf16(sacc[nt * 2 + 0], aH, &bbL[0]);
            mma_bf16(sacc[nt * 2 + 1], aH, &bbL[2]);
            mma_bf16(sacc[nt * 2 + 0], aL, &bbH[0]);
            mma_bf16(sacc[nt * 2 + 1], aL, &bbH[2]);
        }
    }

    int r0 = wm + (lane >> 2);
    int cbase = (lane & 3) * 2;
    #pragma unroll
    for (int h = 0; h < 2; h++) {
        int r = r0 + h * 8;
        if (r < NT) {
            int dn = ddv[r], hn = hhv[r], wn = wwv[r], rg = regn[r];
            #pragma unroll
            for (int t = 0; t < 14; t++) {
                #pragma unroll
                for (int e = 0; e < 2; e++) {
                    int c = t * 8 + cbase + e;
                    if (c < NT) {
                        int idx = (dn - (int)ddv[c] + 1) * 169
                                + (hn - (int)hhv[c] + 6) * 13
                                + (wn - (int)wwv[c] + 6);
                        float mk = (rg != regn[c]) ? -100.f : 0.f;
                        sacc[t][h * 2 + e] += rpb[idx * HEADS + head] + mk;
                    } else {
                        sacc[t][h * 2 + e] = -1e30f;
                    }
                }
            }
        }
    }

    #pragma unroll
    for (int h = 0; h < 2; h++) {
        float mx = -1e30f;
        #pragma unroll
        for (int t = 0; t < 14; t++) {
            mx = fmaxf(mx, sacc[t][h * 2 + 0]);
            mx = fmaxf(mx, sacc[t][h * 2 + 1]);
        }
        mx = fmaxf(mx, __shfl_xor_sync(0xffffffffu, mx, 1));
        mx = fmaxf(mx, __shfl_xor_sync(0xffffffffu, mx, 2));
        float sum = 0.f;
        #pragma unroll
        for (int t = 0; t < 14; t++) {
            #pragma unroll
            for (int e = 0; e < 2; e++) {
                float v = __expf(sacc[t][h * 2 + e] - mx);
                sacc[t][h * 2 + e] = v;
                sum += v;
            }
        }
        sum += __shfl_xor_sync(0xffffffffu, sum, 1);
        sum += __shfl_xor_sync(0xffffffffu, sum, 2);
        float inv = 1.f / sum;
        #pragma unroll
        for (int t = 0; t < 14; t++) {
            sacc[t][h * 2 + 0] *= inv;
            sacc[t][h * 2 + 1] *= inv;
        }
    }

    float oacc[4][4];
    #pragma unroll
    for (int i = 0; i < 4; i++)
        #pragma unroll
        for (int e = 0; e < 4; e++) oacc[i][e] = 0.f;

    #pragma unroll
    for (int j = 0; j < 7; j++) {
        uint32_t aH[4], aL[4];
        #pragma unroll
        for (int q = 0; q < 2; q++) {
            float p0 = sacc[2 * j + q][0], p1 = sacc[2 * j + q][1];
            float p2 = sacc[2 * j + q][2], p3 = sacc[2 * j + q][3];
            aH[q * 2 + 0] = pack2bf(p0, p1);
            aH[q * 2 + 1] = pack2bf(p2, p3);
            aL[q * 2 + 0] = pack2bf(p0 - bf_hi(p0), p1 - bf_hi(p1));
            aL[q * 2 + 1] = pack2bf(p2 - bf_hi(p2), p3 - bf_hi(p3));
        }
        int k0 = j * 16;
        #pragma unroll
        for (int ng = 0; ng < 2; ng++) {
            uint32_t bbH[4], bbL[4];
            uint32_t boff = (uint32_t)(((ng * 16 + bR) * 120 + k0 + bCol) * 2);
            ldsm4(bVh + boff, bbH[0], bbH[1], bbH[2], bbH[3]);
            ldsm4(bVl + boff, bbL[0], bbL[1], bbL[2], bbL[3]);
            mma_bf16(oacc[ng * 2 + 0], aH, &bbH[0]);
            mma_bf16(oacc[ng * 2 + 1], aH, &bbH[2]);
            mma_bf16(oacc[ng * 2 + 0], aH, &bbL[0]);
            mma_bf16(oacc[ng * 2 + 1], aH, &bbL[2]);
            mma_bf16(oacc[ng * 2 + 0], aL, &bbH[0]);
            mma_bf16(oacc[ng * 2 + 1], aL, &bbH[2]);
        }
    }

    // epilogue -> split bf16 planes
    #pragma unroll
    for (int h = 0; h < 2; h++) {
        int r = r0 + h * 8;
        if (r < NT) {
            size_t ob = ((size_t)bwin * NT + r) * Cz + head * HD;
            #pragma unroll
            for (int nt = 0; nt < 4; nt++) {
                int c = nt * 8 + cbase;
                float v0 = oacc[nt][h * 2 + 0], v1 = oacc[nt][h * 2 + 1];
                *(uint32_t*)(g_aoh + ob + c) = pack2bf(v0, v1);
                *(uint32_t*)(g_aol + ob + c) =
                    pack2bf(v0 - bf_hi(v0), v1 - bf_hi(v1));
            }
        }
    }
}

// ---------------- 6: window reverse + unshift + residual + LN2 ----------------
__global__ void k_rev_res_ln2(const float* __restrict__ g2, const float* __restrict__ b2) {
    int t = blockIdx.x;
    int ft = map_token(t);
    int c = threadIdx.x;
    float v = g_po[(size_t)t * Cz + c] + g_xp[(size_t)ft * Cz + c];
    g_xres[(size_t)ft * Cz + c] = v;
    float m, inv;
    blockMeanVar(v, m, inv);
    float o = (v - m) * inv * g2[c] + b2[c];
    float oh = bf_hi(o);
    g_l2h[(size_t)ft * Cz + c] = __float2bfloat16(o);
    g_l2l[(size_t)ft * Cz + c] = __float2bfloat16(o - oh);
}

// ---------------- 9: transpose out (B,D,H,W,C) -> (B,D,C,W,H) ----------------
__global__ void k_transpose_out(float* __restrict__ out) {
    __shared__ float tile[32][33];
    int bz = blockIdx.z;
    int bd = bz / Wz, w = bz % Wz;
    int h0 = blockIdx.x * 32, c0 = blockIdx.y * 32;
    #pragma unroll
    for (int j = 0; j < 32; j += 8) {
        int c = c0 + threadIdx.x;
        int h = h0 + threadIdx.y + j;
        if (h < Hz)
            tile[threadIdx.y + j][threadIdx.x] =
                g_y[(((size_t)bd * Hz + h) * Wz + w) * Cz + c];
    }
    __syncthreads();
    #pragma unroll
    for (int j = 0; j < 32; j += 8) {
        int h = h0 + threadIdx.x;
        int c = c0 + threadIdx.y + j;
        if (h < Hz)
            out[(((size_t)bd * Cz + c) * Wz + w) * Hz + h] =
                tile[threadIdx.x][threadIdx.y + j];
    }
}

// ---------------- launch ----------------
extern "C" void kernel_launch(void* const* d_in, const int* in_sizes, int n_in,
                              void* d_out, int out_size) {
    const float* x      = (const float*)d_in[0];
    const float* n1g    = (const float*)d_in[1];
    const float* n1b    = (const float*)d_in[2];
    const float* qkv_w  = (const float*)d_in[3];
    const float* rpb    = (const float*)d_in[4];
    const float* proj_w = (const float*)d_in[5];
    const float* proj_b = (const float*)d_in[6];
    const float* n2g    = (const float*)d_in[7];
    const float* n2b    = (const float*)d_in[8];
    const float* fc1_w  = (const float*)d_in[9];
    const float* fc1_b  = (const float*)d_in[10];
    const float* fc2_w  = (const float*)d_in[11];
    const float* fc2_b  = (const float*)d_in[12];
    float* out = (float*)d_out;

    void* p;
    cudaGetSymbolAddress(&p, g_qkv);  float* qkv = (float*)p;
    cudaGetSymbolAddress(&p, g_po);   float* po  = (float*)p;
    cudaGetSymbolAddress(&p, g_xres); float* xres = (float*)p;
    cudaGetSymbolAddress(&p, g_y);    float* y = (float*)p;
    cudaGetSymbolAddress(&p, g_xwh);  __nv_bfloat16* xwh = (__nv_bfloat16*)p;
    cudaGetSymbolAddress(&p, g_xwl);  __nv_bfloat16* xwl = (__nv_bfloat16*)p;
    cudaGetSymbolAddress(&p, g_aoh);  __nv_bfloat16* aoh = (__nv_bfloat16*)p;
    cudaGetSymbolAddress(&p, g_aol);  __nv_bfloat16* aol = (__nv_bfloat16*)p;
    cudaGetSymbolAddress(&p, g_l2h);  __nv_bfloat16* l2h = (__nv_bfloat16*)p;
    cudaGetSymbolAddress(&p, g_l2l);  __nv_bfloat16* l2l = (__nv_bfloat16*)p;
    cudaGetSymbolAddress(&p, g_hih);  __nv_bfloat16* hih = (__nv_bfloat16*)p;
    cudaGetSymbolAddress(&p, g_hil);  __nv_bfloat16* hil = (__nv_bfloat16*)p;
    cudaGetSymbolAddress(&p, g_wqh);  __nv_bfloat16* wqh = (__nv_bfloat16*)p;
    cudaGetSymbolAddress(&p, g_wql);  __nv_bfloat16* wql = (__nv_bfloat16*)p;
    cudaGetSymbolAddress(&p, g_wph);  __nv_bfloat16* wph = (__nv_bfloat16*)p;
    cudaGetSymbolAddress(&p, g_wpl);  __nv_bfloat16* wpl = (__nv_bfloat16*)p;
    cudaGetSymbolAddress(&p, g_w1h);  __nv_bfloat16* w1h = (__nv_bfloat16*)p;
    cudaGetSymbolAddress(&p, g_w1l);  __nv_bfloat16* w1l = (__nv_bfloat16*)p;
    cudaGetSymbolAddress(&p, g_w2h);  __nv_bfloat16* w2h = (__nv_bfloat16*)p;
    cudaGetSymbolAddress(&p, g_w2l);  __nv_bfloat16* w2l = (__nv_bfloat16*)p;

    cudaFuncSetAttribute(k_attn_tc, cudaFuncAttributeMaxDynamicSharedMemorySize, ATTN_SMEM_TC);
    cudaFuncSetAttribute(k_gemm_bf<0, false, false, false>, cudaFuncAttributeMaxDynamicSharedMemorySize, GEMM_SMEM);
    cudaFuncSetAttribute(k_gemm_bf<0, true, false, false>,  cudaFuncAttributeMaxDynamicSharedMemorySize, GEMM_SMEM);
    cudaFuncSetAttribute(k_gemm_bf<1, true, false, true>,   cudaFuncAttributeMaxDynamicSharedMemorySize, GEMM_SMEM);
    cudaFuncSetAttribute(k_gemm_bf<0, true, true, false>,   cudaFuncAttributeMaxDynamicSharedMemorySize, GEMM_SMEM);

    dim3 tb(32, 8);
    dim3 tg(3, 8, Bz * Dz * Wz);

    // 0. weight splits (tiny)
    k_wsplit<<<(3 * Cz * Cz + 255) / 256, 256>>>(qkv_w, wqh, wql, 3 * Cz * Cz);
    k_wsplit<<<(Cz * Cz + 255) / 256, 256>>>(proj_w, wph, wpl, Cz * Cz);
    k_wsplit<<<(HID * Cz + 255) / 256, 256>>>(fc1_w, w1h, w1l, HID * Cz);
    k_wsplit<<<(Cz * HID + 255) / 256, 256>>>(fc2_w, w2h, w2l, Cz * HID);
    // 1. transpose in
    k_transpose_in<<<tg, tb>>>(x);
    // 2. LN1 + shift + partition (split bf16 out)
    k_ln_part<<<TOK, 256>>>(n1g, n1b);
    // 3. qkv GEMM
    k_gemm_bf<0, false, false, false><<<dim3((3 * Cz) / 128, TOK / 128), 256, GEMM_SMEM>>>(
        xwh, xwl, wqh, wql, nullptr, nullptr, qkv, nullptr, nullptr, TOK, 3 * Cz, Cz);
    // 4. attention (tensor cores; split bf16 out)
    k_attn_tc<<<dim3(HEADS, BW), 224, ATTN_SMEM_TC>>>(rpb);
    // 5. proj GEMM (+bias) -> g_po fp32
    k_gemm_bf<0, true, false, false><<<dim3(Cz / 128, TOK / 128), 256, GEMM_SMEM>>>(
        aoh, aol, wph, wpl, proj_b, nullptr, po, nullptr, nullptr, TOK, Cz, Cz);
    // 6. reverse + residual + LN2 (split bf16 out)
    k_rev_res_ln2<<<TOK, 256>>>(n2g, n2b);
    // 7. fc1 GEMM + GELU -> split bf16 hid
    k_gemm_bf<1, true, false, true><<<dim3(HID / 128, TOK / 128), 256, GEMM_SMEM>>>(
        l2h, l2l, w1h, w1l, fc1_b, nullptr, nullptr, hih, hil, TOK, HID, Cz);
    // 8. fc2 GEMM + bias + residual -> y fp32
    k_gemm_bf<0, true, true, false><<<dim3(Cz / 128, TOK / 128), 256, GEMM_SMEM>>>(
        hih, hil, w2h, w2l, fc2_b, xres, y, nullptr, nullptr, TOK, Cz, HID);
    // 9. transpose out
    k_transpose_out<<<tg, tb>>>(out);
}

// round 7
// speedup vs baseline: 4.0596x; 1.4310x over previous
#include <cuda_runtime.h>
#include <cuda_bf16.h>
#include <math.h>
#include <stdint.h>

// ---------------- problem constants ----------------
#define Bz 2
#define Dz 8
#define Cz 256
#define Wz 84
#define Hz 84
#define HEADS 8
#define HD 32
#define NT 98            // tokens per window (2*7*7)
#define NTP 112          // padded to 7 x 16
#define NW 576           // windows per batch (4*12*12)
#define BW (Bz*NW)       // 1152 window-batches
#define TOK (BW*NT)      // 112896 tokens
#define HID 1024

// ---------------- scratch (device globals; allocation-free) ----------------
__device__ __align__(256) float g_xp  [(size_t)TOK*Cz];   // shortcut (B,D,H,W,C)
__device__ __align__(256) float g_po  [(size_t)TOK*Cz];   // proj output (windowed order)
__device__ __align__(256) float g_xres[(size_t)TOK*Cz];   // (B,D,H,W,C)
__device__ __align__(256) float g_y   [(size_t)TOK*Cz];
// split bf16 activation planes
__device__ __align__(256) __nv_bfloat16 g_xwh[(size_t)TOK*Cz],   g_xwl[(size_t)TOK*Cz];
__device__ __align__(256) __nv_bfloat16 g_qkvh[(size_t)TOK*3*Cz], g_qkvl[(size_t)TOK*3*Cz];
__device__ __align__(256) __nv_bfloat16 g_aoh[(size_t)TOK*Cz];
__device__ __align__(256) __nv_bfloat16 g_l2h[(size_t)TOK*Cz];
__device__ __align__(256) __nv_bfloat16 g_hih[(size_t)TOK*HID];
// split bf16 weights
__device__ __align__(256) __nv_bfloat16 g_wqh[3*Cz*Cz], g_wql[3*Cz*Cz];
__device__ __align__(256) __nv_bfloat16 g_wph[Cz*Cz],   g_wpl[Cz*Cz];
__device__ __align__(256) __nv_bfloat16 g_w1h[HID*Cz],  g_w1l[HID*Cz];
__device__ __align__(256) __nv_bfloat16 g_w2h[Cz*HID],  g_w2l[Cz*HID];

// ---------------- helpers ----------------
__device__ __forceinline__ uint32_t smem_u32(const void* p) {
    uint32_t a;
    asm("{ .reg .u64 t; cvta.to.shared.u64 t, %1; cvt.u32.u64 %0, t; }" : "=r"(a) : "l"(p));
    return a;
}
__device__ __forceinline__ uint32_t pack2bf(float x, float y) {
    __nv_bfloat162 t = __floats2bfloat162_rn(x, y);
    return *(uint32_t*)&t;
}
__device__ __forceinline__ float bf_hi(float x) {
    return __bfloat162float(__float2bfloat16(x));
}
__device__ __forceinline__ void ldsm4(uint32_t addr, uint32_t& r0, uint32_t& r1,
                                      uint32_t& r2, uint32_t& r3) {
    asm volatile("ldmatrix.sync.aligned.m8n8.x4.shared.b16 {%0,%1,%2,%3}, [%4];"
                 : "=r"(r0), "=r"(r1), "=r"(r2), "=r"(r3) : "r"(addr));
}
__device__ __forceinline__ void ldsm4t(uint32_t addr, uint32_t& r0, uint32_t& r1,
                                       uint32_t& r2, uint32_t& r3) {
    asm volatile("ldmatrix.sync.aligned.m8n8.x4.trans.shared.b16 {%0,%1,%2,%3}, [%4];"
                 : "=r"(r0), "=r"(r1), "=r"(r2), "=r"(r3) : "r"(addr));
}
__device__ __forceinline__ void mma_bf16(float* d, const uint32_t* a, const uint32_t* b) {
    asm volatile(
        "mma.sync.aligned.m16n8k16.row.col.f32.bf16.bf16.f32 "
        "{%0,%1,%2,%3}, {%4,%5,%6,%7}, {%8,%9}, {%0,%1,%2,%3};"
        : "+f"(d[0]), "+f"(d[1]), "+f"(d[2]), "+f"(d[3])
        : "r"(a[0]), "r"(a[1]), "r"(a[2]), "r"(a[3]), "r"(b[0]), "r"(b[1]));
}
__device__ __forceinline__ void cpasync16(uint32_t dst, const void* src) {
    asm volatile("cp.async.cg.shared.global [%0], [%1], 16;" :: "r"(dst), "l"(src));
}

// ---------------- 0: weight split ----------------
__global__ void k_wsplit(const float* __restrict__ src, __nv_bfloat16* __restrict__ hi,
                         __nv_bfloat16* __restrict__ lo, int n) {
    int i = blockIdx.x * 256 + threadIdx.x;
    if (i < n) {
        float v = src[i];
        float h = bf_hi(v);
        hi[i] = __float2bfloat16(v);
        lo[i] = __float2bfloat16(v - h);
    }
}

// ---------------- 1: transpose in (B,D,C,W,H) -> (B,D,H,W,C) ----------------
__global__ void k_transpose_in(const float* __restrict__ x) {
    __shared__ float tile[32][33];
    int bz = blockIdx.z;
    int bd = bz / Wz, w = bz % Wz;
    int h0 = blockIdx.x * 32, c0 = blockIdx.y * 32;
    #pragma unroll
    for (int j = 0; j < 32; j += 8) {
        int c = c0 + threadIdx.y + j;
        int h = h0 + threadIdx.x;
        if (h < Hz)
            tile[threadIdx.y + j][threadIdx.x] =
                x[(((size_t)bd * Cz + c) * Wz + w) * Hz + h];
    }
    __syncthreads();
    #pragma unroll
    for (int j = 0; j < 32; j += 8) {
        int c = c0 + threadIdx.x;
        int h = h0 + threadIdx.y + j;
        if (h < Hz)
            g_xp[(((size_t)bd * Hz + h) * Wz + w) * Cz + c] =
                tile[threadIdx.x][threadIdx.y + j];
    }
}

__device__ __forceinline__ int map_token(int t) {
    int b   = t / (NW * NT);
    int rem = t % (NW * NT);
    int wi = rem / NT, n = rem % NT;
    int d2 = wi / 144, h2 = (wi / 12) % 12, w2 = wi % 12;
    int dd = n / 49, r = n % 49, hh = r / 7, ww = r % 7;
    int d = d2 * 2 + dd, h = h2 * 7 + hh, w = w2 * 7 + ww;
    int ds = (d + 1) & 7;
    int hs = h + 3; if (hs >= Hz) hs -= Hz;
    int ws = w + 3; if (ws >= Wz) ws -= Wz;
    return ((b * Dz + ds) * Hz + hs) * Wz + ws;
}

__device__ __forceinline__ void blockMeanVar(float v, float& mean, float& invstd) {
    __shared__ float sbuf[16];
    float s1 = v, s2 = v * v;
    #pragma unroll
    for (int o = 16; o; o >>= 1) {
        s1 += __shfl_down_sync(0xffffffffu, s1, o);
        s2 += __shfl_down_sync(0xffffffffu, s2, o);
    }
    int wp = threadIdx.x >> 5, ln = threadIdx.x & 31;
    if (!ln) { sbuf[wp] = s1; sbuf[8 + wp] = s2; }
    __syncthreads();
    float m = 0.f, q = 0.f;
    #pragma unroll
    for (int i = 0; i < 8; i++) { m += sbuf[i]; q += sbuf[8 + i]; }
    m *= (1.f / Cz);
    q = q * (1.f / Cz) - m * m;
    mean = m;
    invstd = rsqrtf(q + 1e-5f);
}

// ---------------- 2: LN1 + shift + partition -> split bf16 ----------------
__global__ void k_ln_part(const float* __restrict__ g, const float* __restrict__ bta) {
    int t = blockIdx.x;
    int srct = map_token(t);
    int c = threadIdx.x;
    float v = g_xp[(size_t)srct * Cz + c];
    float m, inv;
    blockMeanVar(v, m, inv);
    float o = (v - m) * inv * g[c] + bta[c];
    float oh = bf_hi(o);
    g_xwh[(size_t)t * Cz + c] = __float2bfloat16(o);
    g_xwl[(size_t)t * Cz + c] = __float2bfloat16(o - oh);
}

// ---------------- GEMM: out[M,N] = A[M,K] @ Wt[N,K]^T --------------------
// PASSES=3: split-bf16 (hi/lo), 3 mma passes. PASSES=1: plain bf16 hi only.
// OSPLIT: 0 = fp32 out, 1 = bf16 hi+lo planes, 2 = bf16 hi plane only.
#define PADK 40
#define PLANE_B (128 * PADK * 2)       // 10240 bytes
template <int PASSES, int ACT, bool HAS_BIAS, bool HAS_RES, int OSPLIT>
__global__ __launch_bounds__(256, 2) void k_gemm_bf(
    const __nv_bfloat16* __restrict__ Ah, const __nv_bfloat16* __restrict__ Al,
    const __nv_bfloat16* __restrict__ Bh, const __nv_bfloat16* __restrict__ Bl,
    const float* __restrict__ bias, const float* __restrict__ res,
    float* __restrict__ out,
    __nv_bfloat16* __restrict__ outh, __nv_bfloat16* __restrict__ outl,
    int M, int N, int K) {
    extern __shared__ __align__(16) unsigned char dsm[];
    constexpr int NPL = (PASSES == 3) ? 4 : 2;       // planes per stage
    constexpr int STB = NPL * PLANE_B;
    uint32_t sbase = smem_u32(dsm);
    int tid = threadIdx.x, lane = tid & 31, wid = tid >> 5;
    int bm = blockIdx.y * 128, bn = blockIdx.x * 128;
    int wm = (wid & 1) * 64, wn = (wid >> 1) * 32;

    int aRow = wm + (lane & 15);
    int aCol = (lane >> 4) * 8;
    int bRow = wn + ((lane >> 4) << 3) + (lane & 7);
    int bCol = ((lane >> 3) & 1) * 8;

    float acc[4][4][4];
    #pragma unroll
    for (int i = 0; i < 4; i++)
        #pragma unroll
        for (int j = 0; j < 4; j++)
            #pragma unroll
            for (int c = 0; c < 4; c++) acc[i][j][c] = 0.f;

    const int nChunks = K >> 5;

    #define ISSUE(ch, s) do {                                                   \
        int k0_ = (ch) << 5;                                                    \
        uint32_t sb_ = sbase + (s) * STB;                                       \
        _Pragma("unroll")                                                       \
        for (int q_ = 0; q_ < 2; q_++) {                                        \
            int j_ = q_ * 256 + tid;                                            \
            int row_ = j_ >> 2, c8_ = (j_ & 3) * 8;                             \
            uint32_t so_ = (uint32_t)((row_ * PADK + c8_) * 2);                 \
            size_t ga_ = (size_t)(bm + row_) * K + k0_ + c8_;                   \
            size_t gb_ = (size_t)(bn + row_) * K + k0_ + c8_;                   \
            cpasync16(sb_ + 0 * PLANE_B + so_, Ah + ga_);                       \
            if (PASSES == 3) cpasync16(sb_ + 1 * PLANE_B + so_, Al + ga_);      \
            cpasync16(sb_ + (PASSES == 3 ? 2 : 1) * PLANE_B + so_, Bh + gb_);   \
            if (PASSES == 3) cpasync16(sb_ + 3 * PLANE_B + so_, Bl + gb_);      \
        }                                                                       \
        asm volatile("cp.async.commit_group;");                                 \
    } while (0)

    ISSUE(0, 0);
    for (int ch = 0; ch < nChunks; ch++) {
        int s = ch & 1;
        if (ch + 1 < nChunks) {
            ISSUE(ch + 1, (ch + 1) & 1);
            asm volatile("cp.async.wait_group 1;");
        } else {
            asm volatile("cp.async.wait_group 0;");
        }
        __syncthreads();

        uint32_t baseAH = sbase + s * STB;
        uint32_t baseAL = baseAH + PLANE_B;
        uint32_t baseBH = baseAH + (PASSES == 3 ? 2 : 1) * PLANE_B;
        uint32_t baseBL = baseAH + 3 * PLANE_B;

        #pragma unroll
        for (int kk = 0; kk < 2; kk++) {
            int k0 = kk * 16;
            uint32_t aH[4][4], aL[4][4], bb[8];
            #pragma unroll
            for (int mi = 0; mi < 4; mi++) {
                uint32_t off = (uint32_t)(((aRow + mi * 16) * PADK + k0 + aCol) * 2);
                ldsm4(baseAH + off, aH[mi][0], aH[mi][1], aH[mi][2], aH[mi][3]);
                if (PASSES == 3)
                    ldsm4(baseAL + off, aL[mi][0], aL[mi][1], aL[mi][2], aL[mi][3]);
            }
            #pragma unroll
            for (int p = 0; p < 2; p++) {
                uint32_t off = (uint32_t)(((bRow + p * 16) * PADK + k0 + bCol) * 2);
                ldsm4(baseBH + off, bb[p * 4 + 0], bb[p * 4 + 1], bb[p * 4 + 2], bb[p * 4 + 3]);
            }
            #pragma unroll
            for (int mi = 0; mi < 4; mi++)
                #pragma unroll
                for (int ni = 0; ni < 4; ni++)
                    mma_bf16(acc[mi][ni], aH[mi], &bb[ni * 2]);
            if (PASSES == 3) {
                #pragma unroll
                for (int mi = 0; mi < 4; mi++)
                    #pragma unroll
                    for (int ni = 0; ni < 4; ni++)
                        mma_bf16(acc[mi][ni], aL[mi], &bb[ni * 2]);
                #pragma unroll
                for (int p = 0; p < 2; p++) {
                    uint32_t off = (uint32_t)(((bRow + p * 16) * PADK + k0 + bCol) * 2);
                    ldsm4(baseBL + off, bb[p * 4 + 0], bb[p * 4 + 1], bb[p * 4 + 2], bb[p * 4 + 3]);
                }
                #pragma unroll
                for (int mi = 0; mi < 4; mi++)
                    #pragma unroll
                    for (int ni = 0; ni < 4; ni++)
                        mma_bf16(acc[mi][ni], aH[mi], &bb[ni * 2]);
            }
        }
        __syncthreads();
    }
    #undef ISSUE

    int orow = lane >> 2, ocol = (lane & 3) * 2;
    #pragma unroll
    for (int mi = 0; mi < 4; mi++) {
        int m0 = bm + wm + mi * 16;
        #pragma unroll
        for (int ni = 0; ni < 4; ni++) {
            int n = bn + wn + ni * 8 + ocol;
            float bi0 = 0.f, bi1 = 0.f;
            if (HAS_BIAS) { bi0 = bias[n]; bi1 = bias[n + 1]; }
            #pragma unroll
            for (int half = 0; half < 2; half++) {
                int m = m0 + orow + half * 8;
                float v0 = acc[mi][ni][half * 2 + 0] + bi0;
                float v1 = acc[mi][ni][half * 2 + 1] + bi1;
                if (ACT == 1) {
                    v0 = 0.5f * v0 * (1.f + erff(v0 * 0.70710678118654752f));
                    v1 = 0.5f * v1 * (1.f + erff(v1 * 0.70710678118654752f));
                }
                if (HAS_RES) {
                    const float2 r2 = *(const float2*)(res + (size_t)m * N + n);
                    v0 += r2.x; v1 += r2.y;
                }
                if (OSPLIT == 1) {
                    *(uint32_t*)(outh + (size_t)m * N + n) = pack2bf(v0, v1);
                    *(uint32_t*)(outl + (size_t)m * N + n) =
                        pack2bf(v0 - bf_hi(v0), v1 - bf_hi(v1));
                } else if (OSPLIT == 2) {
                    *(uint32_t*)(outh + (size_t)m * N + n) = pack2bf(v0, v1);
                } else {
                    *(float2*)(out + (size_t)m * N + n) = make_float2(v0, v1);
                }
            }
        }
    }
}

// ---------------- 4: tensor-core attention per (head, window) ----------------
// planes (each NTP x 40 halves): Qh Ql Kh Kl Vh Vl; V stored natural [m][d],
// loaded with ldmatrix.trans. Q scale folded into the bias step post-mma.
#define APL (NTP * 40)                 // 4480 halves per plane
#define ATTN_SMEM_TC (6 * APL * 2)     // 53760 bytes
__global__ __launch_bounds__(224, 2) void k_attn_tc(const float* __restrict__ rpb) {
    extern __shared__ __nv_bfloat16 asm_[];
    __shared__ unsigned char ddv[NTP], hhv[NTP], wwv[NTP];
    __shared__ int regn[NTP];

    int head = blockIdx.x, bwin = blockIdx.y;
    int tid = threadIdx.x, lane = tid & 31, wid = tid >> 5;
    const float scale = 0.17677669529663687f;
    uint32_t sbase = smem_u32(asm_);

    // zero pad rows 98..111 of all 6 planes (14 rows x 40 halves = 280 u32/plane)
    for (int i = tid; i < 6 * 280; i += 224) {
        int p = i / 280, r = i % 280;
        ((uint32_t*)(asm_ + p * APL + NT * 40))[r] = 0u;
    }
    if (tid < NTP) {
        if (tid < NT) {
            int wi = bwin % NW;
            int dd = tid / 49, r = tid % 49, hh = r / 7, ww = r % 7;
            ddv[tid] = (unsigned char)dd; hhv[tid] = (unsigned char)hh; wwv[tid] = (unsigned char)ww;
            int gd = (wi / 144) * 2 + dd;
            int gh = ((wi / 12) % 12) * 7 + hh;
            int gw = (wi % 12) * 7 + ww;
            int rd = gd < 6  ? 0 : (gd < 7  ? 1 : 2);
            int rh = gh < 77 ? 0 : (gh < 81 ? 1 : 2);
            int rw = gw < 77 ? 0 : (gw < 81 ? 1 : 2);
            regn[tid] = rd * 9 + rh * 3 + rw;
        } else {
            ddv[tid] = hhv[tid] = wwv[tid] = 0; regn[tid] = -1;
        }
    }

    // fill: 98 tokens x {q,k,v} x {hi,lo} x 4 x 16B  pure cp.async copies
    for (int i = tid; i < 98 * 6 * 4; i += 224) {
        int chunk = i & 3;
        int idx = i >> 2;                 // 0..587
        int n = idx / 6, which = idx % 6;
        int sel = which >> 1, pl = which & 1;
        const __nv_bfloat16* src = (pl ? g_qkvl : g_qkvh)
            + (size_t)(bwin * NT + n) * (3 * Cz) + sel * Cz + head * HD + chunk * 8;
        uint32_t dst = sbase + (uint32_t)(((sel * 2 + pl) * APL + n * 40 + chunk * 8) * 2);
        cpasync16(dst, src);
    }
    asm volatile("cp.async.commit_group;");
    asm volatile("cp.async.wait_group 0;");
    __syncthreads();

    uint32_t bQh = sbase,            bQl = sbase + APL * 2;
    uint32_t bKh = sbase + 2*APL*2,  bKl = sbase + 3*APL*2;
    uint32_t bVh = sbase + 4*APL*2,  bVl = sbase + 5*APL*2;

    int wm = wid * 16;
    int aRow = wm + (lane & 15);
    int aCol = (lane >> 4) * 8;
    int bR = ((lane >> 4) << 3) + (lane & 7);
    int bCol = ((lane >> 3) & 1) * 8;
    // trans-ldmatrix lane addressing for V [m][d]
    int vR = ((lane >> 3) & 1) * 8 + (lane & 7);
    int vCol = (lane >> 4) * 8;

    float sacc[14][4];
    #pragma unroll
    for (int t = 0; t < 14; t++)
        #pragma unroll
        for (int e = 0; e < 4; e++) sacc[t][e] = 0.f;

    #pragma unroll
    for (int kk = 0; kk < 2; kk++) {
        int k0 = kk * 16;
        uint32_t aH[4], aL[4], bbH[4], bbL[4];
        uint32_t aoff = (uint32_t)((aRow * 40 + k0 + aCol) * 2);
        ldsm4(bQh + aoff, aH[0], aH[1], aH[2], aH[3]);
        ldsm4(bQl + aoff, aL[0], aL[1], aL[2], aL[3]);
        #pragma unroll
        for (int nt = 0; nt < 7; nt++) {
            uint32_t boff = (uint32_t)(((nt * 16 + bR) * 40 + k0 + bCol) * 2);
            ldsm4(bKh + boff, bbH[0], bbH[1], bbH[2], bbH[3]);
            ldsm4(bKl + boff, bbL[0], bbL[1], bbL[2], bbL[3]);
            mma_bf16(sacc[nt * 2 + 0], aH, &bbH[0]);
            mma_bf16(sacc[nt * 2 + 1], aH, &bbH[2]);
            mma_bf16(sacc[nt * 2 + 0], aH, &bbL[0]);
            mma_bf16(sacc[nt * 2 + 1], aH, &bbL[2]);
            mma_bf16(sacc[nt * 2 + 0], aL, &bbH[0]);
            mma_bf16(sacc[nt * 2 + 1], aL, &bbH[2]);
        }
    }

    // scale + bias + mask (in regs)
    int r0 = wm + (lane >> 2);
    int cbase = (lane & 3) * 2;
    #pragma unroll
    for (int h = 0; h < 2; h++) {
        int r = r0 + h * 8;
        if (r < NT) {
            int dn = ddv[r], hn = hhv[r], wn = wwv[r], rg = regn[r];
            #pragma unroll
            for (int t = 0; t < 14; t++) {
                #pragma unroll
                for (int e = 0; e < 2; e++) {
                    int c = t * 8 + cbase + e;
                    if (c < NT) {
                        int idx = (dn - (int)ddv[c] + 1) * 169
                                + (hn - (int)hhv[c] + 6) * 13
                                + (wn - (int)wwv[c] + 6);
                        float mk = (rg != regn[c]) ? -100.f : 0.f;
                        sacc[t][h * 2 + e] = sacc[t][h * 2 + e] * scale
                                           + rpb[idx * HEADS + head] + mk;
                    } else {
                        sacc[t][h * 2 + e] = -1e30f;
                    }
                }
            }
        }
    }

    // softmax in regs (row = quad of lanes)
    #pragma unroll
    for (int h = 0; h < 2; h++) {
        float mx = -1e30f;
        #pragma unroll
        for (int t = 0; t < 14; t++) {
            mx = fmaxf(mx, sacc[t][h * 2 + 0]);
            mx = fmaxf(mx, sacc[t][h * 2 + 1]);
        }
        mx = fmaxf(mx, __shfl_xor_sync(0xffffffffu, mx, 1));
        mx = fmaxf(mx, __shfl_xor_sync(0xffffffffu, mx, 2));
        float sum = 0.f;
        #pragma unroll
        for (int t = 0; t < 14; t++) {
            #pragma unroll
            for (int e = 0; e < 2; e++) {
                float v = __expf(sacc[t][h * 2 + e] - mx);
                sacc[t][h * 2 + e] = v;
                sum += v;
            }
        }
        sum += __shfl_xor_sync(0xffffffffu, sum, 1);
        sum += __shfl_xor_sync(0xffffffffu, sum, 2);
        float inv = 1.f / sum;
        #pragma unroll
        for (int t = 0; t < 14; t++) {
            sacc[t][h * 2 + 0] *= inv;
            sacc[t][h * 2 + 1] *= inv;
        }
    }

    // P @ V : P a-frags from sacc; V via trans-ldmatrix (3-pass)
    float oacc[4][4];
    #pragma unroll
    for (int i = 0; i < 4; i++)
        #pragma unroll
        for (int e = 0; e < 4; e++) oacc[i][e] = 0.f;

    #pragma unroll
    for (int j = 0; j < 7; j++) {
        uint32_t aH[4], aL[4];
        #pragma unroll
        for (int q = 0; q < 2; q++) {
            float p0 = sacc[2 * j + q][0], p1 = sacc[2 * j + q][1];
            float p2 = sacc[2 * j + q][2], p3 = sacc[2 * j + q][3];
            aH[q * 2 + 0] = pack2bf(p0, p1);
            aH[q * 2 + 1] = pack2bf(p2, p3);
            aL[q * 2 + 0] = pack2bf(p0 - bf_hi(p0), p1 - bf_hi(p1));
            aL[q * 2 + 1] = pack2bf(p2 - bf_hi(p2), p3 - bf_hi(p3));
        }
        #pragma unroll
        for (int dg = 0; dg < 2; dg++) {
            uint32_t bbH[4], bbL[4];
            uint32_t boff = (uint32_t)(((j * 16 + vR) * 40 + vCol + dg * 16) * 2);
            ldsm4t(bVh + boff, bbH[0], bbH[1], bbH[2], bbH[3]);
            ldsm4t(bVl + boff, bbL[0], bbL[1], bbL[2], bbL[3]);
            mma_bf16(oacc[dg * 2 + 0], aH, &bbH[0]);
            mma_bf16(oacc[dg * 2 + 1], aH, &bbH[2]);
            mma_bf16(oacc[dg * 2 + 0], aH, &bbL[0]);
            mma_bf16(oacc[dg * 2 + 1], aH, &bbL[2]);
            mma_bf16(oacc[dg * 2 + 0], aL, &bbH[0]);
            mma_bf16(oacc[dg * 2 + 1], aL, &bbH[2]);
        }
    }

    // epilogue -> hi plane only (proj is 1-pass)
    #pragma unroll
    for (int h = 0; h < 2; h++) {
        int r = r0 + h * 8;
        if (r < NT) {
            size_t ob = ((size_t)bwin * NT + r) * Cz + head * HD;
            #pragma unroll
            for (int nt = 0; nt < 4; nt++) {
                int c = nt * 8 + cbase;
                *(uint32_t*)(g_aoh + ob + c) =
                    pack2bf(oacc[nt][h * 2 + 0], oacc[nt][h * 2 + 1]);
            }
        }
    }
}

// ---------------- 6: window reverse + unshift + residual + LN2 ----------------
__global__ void k_rev_res_ln2(const float* __restrict__ g2, const float* __restrict__ b2) {
    int t = blockIdx.x;
    int ft = map_token(t);
    int c = threadIdx.x;
    float v = g_po[(size_t)t * Cz + c] + g_xp[(size_t)ft * Cz + c];
    g_xres[(size_t)ft * Cz + c] = v;
    float m, inv;
    blockMeanVar(v, m, inv);
    float o = (v - m) * inv * g2[c] + b2[c];
    g_l2h[(size_t)ft * Cz + c] = __float2bfloat16(o);
}

// ---------------- 9: transpose out (B,D,H,W,C) -> (B,D,C,W,H) ----------------
__global__ void k_transpose_out(float* __restrict__ out) {
    __shared__ float tile[32][33];
    int bz = blockIdx.z;
    int bd = bz / Wz, w = bz % Wz;
    int h0 = blockIdx.x * 32, c0 = blockIdx.y * 32;
    #pragma unroll
    for (int j = 0; j < 32; j += 8) {
        int c = c0 + threadIdx.x;
        int h = h0 + threadIdx.y + j;
        if (h < Hz)
            tile[threadIdx.y + j][threadIdx.x] =
                g_y[(((size_t)bd * Hz + h) * Wz + w) * Cz + c];
    }
    __syncthreads();
    #pragma unroll
    for (int j = 0; j < 32; j += 8) {
        int h = h0 + threadIdx.x;
        int c = c0 + threadIdx.y + j;
        if (h < Hz)
            out[(((size_t)bd * Cz + c) * Wz + w) * Hz + h] =
                tile[threadIdx.x][threadIdx.y + j];
    }
}

// ---------------- launch ----------------
extern "C" void kernel_launch(void* const* d_in, const int* in_sizes, int n_in,
                              void* d_out, int out_size) {
    const float* x      = (const float*)d_in[0];
    const float* n1g    = (const float*)d_in[1];
    const float* n1b    = (const float*)d_in[2];
    const float* qkv_w  = (const float*)d_in[3];
    const float* rpb    = (const float*)d_in[4];
    const float* proj_w = (const float*)d_in[5];
    const float* proj_b = (const float*)d_in[6];
    const float* n2g    = (const float*)d_in[7];
    const float* n2b    = (const float*)d_in[8];
    const float* fc1_w  = (const float*)d_in[9];
    const float* fc1_b  = (const float*)d_in[10];
    const float* fc2_w  = (const float*)d_in[11];
    const float* fc2_b  = (const float*)d_in[12];
    float* out = (float*)d_out;

    void* p;
    cudaGetSymbolAddress(&p, g_po);   float* po   = (float*)p;
    cudaGetSymbolAddress(&p, g_xres); float* xres = (float*)p;
    cudaGetSymbolAddress(&p, g_y);    float* y    = (float*)p;
    cudaGetSymbolAddress(&p, g_xwh);  __nv_bfloat16* xwh = (__nv_bfloat16*)p;
    cudaGetSymbolAddress(&p, g_xwl);  __nv_bfloat16* xwl = (__nv_bfloat16*)p;
    cudaGetSymbolAddress(&p, g_qkvh); __nv_bfloat16* qkvh = (__nv_bfloat16*)p;
    cudaGetSymbolAddress(&p, g_qkvl); __nv_bfloat16* qkvl = (__nv_bfloat16*)p;
    cudaGetSymbolAddress(&p, g_aoh);  __nv_bfloat16* aoh = (__nv_bfloat16*)p;
    cudaGetSymbolAddress(&p, g_l2h);  __nv_bfloat16* l2h = (__nv_bfloat16*)p;
    cudaGetSymbolAddress(&p, g_hih);  __nv_bfloat16* hih = (__nv_bfloat16*)p;
    cudaGetSymbolAddress(&p, g_wqh);  __nv_bfloat16* wqh = (__nv_bfloat16*)p;
    cudaGetSymbolAddress(&p, g_wql);  __nv_bfloat16* wql = (__nv_bfloat16*)p;
    cudaGetSymbolAddress(&p, g_wph);  __nv_bfloat16* wph = (__nv_bfloat16*)p;
    cudaGetSymbolAddress(&p, g_wpl);  __nv_bfloat16* wpl = (__nv_bfloat16*)p;
    cudaGetSymbolAddress(&p, g_w1h);  __nv_bfloat16* w1h = (__nv_bfloat16*)p;
    cudaGetSymbolAddress(&p, g_w1l);  __nv_bfloat16* w1l = (__nv_bfloat16*)p;
    cudaGetSymbolAddress(&p, g_w2h);  __nv_bfloat16* w2h = (__nv_bfloat16*)p;
    cudaGetSymbolAddress(&p, g_w2l);  __nv_bfloat16* w2l = (__nv_bfloat16*)p;

    cudaFuncSetAttribute(k_attn_tc, cudaFuncAttributeMaxDynamicSharedMemorySize, ATTN_SMEM_TC);
    cudaFuncSetAttribute(k_gemm_bf<3, 0, false, false, 1>, cudaFuncAttributeMaxDynamicSharedMemorySize, 8 * PLANE_B);
    cudaFuncSetAttribute(k_gemm_bf<1, 0, true, false, 0>,  cudaFuncAttributeMaxDynamicSharedMemorySize, 4 * PLANE_B);
    cudaFuncSetAttribute(k_gemm_bf<1, 1, true, false, 2>,  cudaFuncAttributeMaxDynamicSharedMemorySize, 4 * PLANE_B);
    cudaFuncSetAttribute(k_gemm_bf<1, 0, true, true, 0>,   cudaFuncAttributeMaxDynamicSharedMemorySize, 4 * PLANE_B);

    dim3 tb(32, 8);
    dim3 tg(3, 8, Bz * Dz * Wz);

    // 0. weight splits (tiny)
    k_wsplit<<<(3 * Cz * Cz + 255) / 256, 256>>>(qkv_w, wqh, wql, 3 * Cz * Cz);
    k_wsplit<<<(Cz * Cz + 255) / 256, 256>>>(proj_w, wph, wpl, Cz * Cz);
    k_wsplit<<<(HID * Cz + 255) / 256, 256>>>(fc1_w, w1h, w1l, HID * Cz);
    k_wsplit<<<(Cz * HID + 255) / 256, 256>>>(fc2_w, w2h, w2l, Cz * HID);
    // 1. transpose in
    k_transpose_in<<<tg, tb>>>(x);
    // 2. LN1 + shift + partition (split bf16 out)
    k_ln_part<<<TOK, 256>>>(n1g, n1b);
    // 3. qkv GEMM (3-pass, split bf16 out)
    k_gemm_bf<3, 0, false, false, 1><<<dim3((3 * Cz) / 128, TOK / 128), 256, 8 * PLANE_B>>>(
        xwh, xwl, wqh, wql, nullptr, nullptr, nullptr, qkvh, qkvl, TOK, 3 * Cz, Cz);
    // 4. attention (tensor cores, 3-pass)
    k_attn_tc<<<dim3(HEADS, BW), 224, ATTN_SMEM_TC>>>(rpb);
    // 5. proj GEMM (1-pass, +bias) -> g_po fp32
    k_gemm_bf<1, 0, true, false, 0><<<dim3(Cz / 128, TOK / 128), 256, 4 * PLANE_B>>>(
        aoh, nullptr, wph, nullptr, proj_b, nullptr, po, nullptr, nullptr, TOK, Cz, Cz);
    // 6. reverse + residual + LN2 (hi plane out)
    k_rev_res_ln2<<<TOK, 256>>>(n2g, n2b);
    // 7. fc1 GEMM (1-pass) + GELU -> hi plane
    k_gemm_bf<1, 1, true, false, 2><<<dim3(HID / 128, TOK / 128), 256, 4 * PLANE_B>>>(
        l2h, nullptr, w1h, nullptr, fc1_b, nullptr, nullptr, hih, nullptr, TOK, HID, Cz);
    // 8. fc2 GEMM (1-pass) + bias + residual -> y fp32
    k_gemm_bf<1, 0, true, true, 0><<<dim3(Cz / 128, TOK / 128), 256, 4 * PLANE_B>>>(
        hih, nullptr, w2h, nullptr, fc2_b, xres, y, nullptr, nullptr, TOK, Cz, HID);
    // 9. transpose out
    k_transpose_out<<<tg, tb>>>(out);
}